// round 1
// baseline (speedup 1.0000x reference)
#include <cuda_runtime.h>

#define CI 128
#define CO 128
#define NE 4
#define MAXROWS (2048*128)
#define BM 128
#define TM 8
#define TN 8
#define XS_STRIDE (CI + 1)   // pad: a-frag consumers hit different banks (8*129 % 32 = 8)

// Scratch: per-expert gathered row index lists + counts (no dynamic alloc allowed)
__device__ int g_row_idx[NE][MAXROWS];
__device__ int g_count[NE];

__global__ void k_reset() {
    if (threadIdx.x < NE) g_count[threadIdx.x] = 0;
}

// Bucket rows by expert using warp-aggregated atomics (avoid 262144-way
// single-address ATOMG contention -> ~8K atomics per expert instead).
__global__ void k_scatter(const int* __restrict__ atom_numbers,
                          const int* __restrict__ atom_cases, int nrows) {
    int row = blockIdx.x * blockDim.x + threadIdx.x;
    bool valid = row < nrows;
    int an = valid ? atom_numbers[row] : -1234567;
    int c0 = __ldg(atom_cases + 0);
    int c1 = __ldg(atom_cases + 1);
    int c2 = __ldg(atom_cases + 2);
    int c3 = __ldg(atom_cases + 3);
    int e = -1;
    if (an == c0) e = 0;
    else if (an == c1) e = 1;
    else if (an == c2) e = 2;
    else if (an == c3) e = 3;

    unsigned lane = threadIdx.x & 31u;
#pragma unroll
    for (int ee = 0; ee < NE; ee++) {
        unsigned m = __ballot_sync(0xffffffffu, e == ee);
        if (e == ee) {
            int leader = __ffs(m) - 1;
            int base = 0;
            if ((int)lane == leader) base = atomicAdd(&g_count[ee], __popc(m));
            base = __shfl_sync(m, base, leader);
            int pos = base + __popc(m & ((1u << lane) - 1u));
            g_row_idx[ee][pos] = row;
        }
    }
}

// Zero output rows whose atom number matches no expert (out is poisoned 0xAA).
// One thread per float4 (32 threads per row) -> coalesced, warp-uniform branch.
__global__ void k_zero(float* __restrict__ out,
                       const int* __restrict__ atom_numbers,
                       const int* __restrict__ atom_cases, int nrows) {
    int i4 = blockIdx.x * blockDim.x + threadIdx.x;
    int total4 = nrows * (CO / 4);
    if (i4 >= total4) return;
    int row = i4 / (CO / 4);
    int an = __ldg(atom_numbers + row);
    bool matched = (an == __ldg(atom_cases + 0)) | (an == __ldg(atom_cases + 1)) |
                   (an == __ldg(atom_cases + 2)) | (an == __ldg(atom_cases + 3));
    if (!matched) {
        ((float4*)out)[i4] = make_float4(0.f, 0.f, 0.f, 0.f);
    }
}

// Grouped SGEMM: block handles up to 128 rows of ONE expert (gathered) x 128 outputs, K=128.
// W[e] (64KB) + gathered x tile (64.5KB) fully resident in smem. 16x16 threads, 8x8 tiles.
__global__ void __launch_bounds__(256, 1)
k_gemm(const float* __restrict__ x, const float* __restrict__ W,
       const float* __restrict__ bias, float* __restrict__ out, int nrows) {
    int e = blockIdx.y;
    int cnt = g_count[e];
    int m0 = blockIdx.x * BM;
    if (m0 >= cnt) return;
    int nr = min(BM, cnt - m0);

    extern __shared__ float smem[];
    float* xs = smem;                      // [BM][XS_STRIDE]
    float* ws = smem + BM * XS_STRIDE;     // [CI][CO]

    int t = threadIdx.x;

    // Load W[e]: 16384 floats, 256 threads * 16 float4, coalesced (L2-resident after wave 1)
    {
        const float4* Wg = (const float4*)(W + (size_t)e * CI * CO);
        float4* ws4 = (float4*)ws;
#pragma unroll
        for (int i = 0; i < 16; i++) ws4[t + i * 256] = Wg[t + i * 256];
    }

    // Gather x rows: each of 8 warps loads 16 rows; one float4 per lane per row.
    {
        int warp = t >> 5, lane = t & 31;
        for (int rr = warp; rr < BM; rr += 8) {
            float4 v = make_float4(0.f, 0.f, 0.f, 0.f);
            if (rr < nr) {
                int grow = __ldg(&g_row_idx[e][m0 + rr]);
                v = ((const float4*)(x + (size_t)grow * CI))[lane];
            }
            float* dst = xs + rr * XS_STRIDE + lane * 4;
            dst[0] = v.x; dst[1] = v.y; dst[2] = v.z; dst[3] = v.w;
        }
    }
    __syncthreads();

    int tx = t & 15, ty = t >> 4;
    int r0 = ty * TM, o0 = tx * TN;

    float acc[TM][TN];
#pragma unroll
    for (int u = 0; u < TM; u++)
#pragma unroll
        for (int v = 0; v < TN; v++) acc[u][v] = 0.f;

#pragma unroll 4
    for (int k = 0; k < CI; k++) {
        float a[TM];
#pragma unroll
        for (int u = 0; u < TM; u++) a[u] = xs[(r0 + u) * XS_STRIDE + k];
        float4 b0 = *(const float4*)(ws + k * CO + o0);
        float4 b1 = *(const float4*)(ws + k * CO + o0 + 4);
        float bb[TN] = {b0.x, b0.y, b0.z, b0.w, b1.x, b1.y, b1.z, b1.w};
#pragma unroll
        for (int u = 0; u < TM; u++)
#pragma unroll
            for (int v = 0; v < TN; v++) acc[u][v] += a[u] * bb[v];
    }

    // Epilogue: +bias, relu, scatter-store float4s to gathered row positions.
    float bia[TN];
    {
        float4 q0 = *(const float4*)(bias + e * CO + o0);
        float4 q1 = *(const float4*)(bias + e * CO + o0 + 4);
        bia[0] = q0.x; bia[1] = q0.y; bia[2] = q0.z; bia[3] = q0.w;
        bia[4] = q1.x; bia[5] = q1.y; bia[6] = q1.z; bia[7] = q1.w;
    }
#pragma unroll
    for (int u = 0; u < TM; u++) {
        int ro = r0 + u;
        if (ro < nr) {
            int grow = __ldg(&g_row_idx[e][m0 + ro]);
            float* op = out + (size_t)grow * CO + o0;
            float4 w0, w1;
            w0.x = fmaxf(acc[u][0] + bia[0], 0.f);
            w0.y = fmaxf(acc[u][1] + bia[1], 0.f);
            w0.z = fmaxf(acc[u][2] + bia[2], 0.f);
            w0.w = fmaxf(acc[u][3] + bia[3], 0.f);
            w1.x = fmaxf(acc[u][4] + bia[4], 0.f);
            w1.y = fmaxf(acc[u][5] + bia[5], 0.f);
            w1.z = fmaxf(acc[u][6] + bia[6], 0.f);
            w1.w = fmaxf(acc[u][7] + bia[7], 0.f);
            *(float4*)(op) = w0;
            *(float4*)(op + 4) = w1;
        }
    }
}

extern "C" void kernel_launch(void* const* d_in, const int* in_sizes, int n_in,
                              void* d_out, int out_size) {
    const float* x = (const float*)d_in[0];
    const int* atom_numbers = (const int*)d_in[1];
    const float* W = (const float*)d_in[2];
    const float* bias = (const float*)d_in[3];
    const int* atom_cases = (const int*)d_in[4];
    float* out = (float*)d_out;

    int nrows = in_sizes[1];  // B * A

    k_reset<<<1, 32>>>();
    k_scatter<<<(nrows + 255) / 256, 256>>>(atom_numbers, atom_cases, nrows);

    int total4 = nrows * (CO / 4);
    k_zero<<<(total4 + 255) / 256, 256>>>(out, atom_numbers, atom_cases, nrows);

    size_t smem = (size_t)(BM * XS_STRIDE + CI * CO) * sizeof(float);
    cudaFuncSetAttribute(k_gemm, cudaFuncAttributeMaxDynamicSharedMemorySize, (int)smem);
    dim3 grid((nrows + BM - 1) / BM, NE);
    k_gemm<<<grid, 256, smem>>>(x, W, bias, out, nrows);
}

// round 3
// speedup vs baseline: 1.4555x; 1.4555x over previous
#include <cuda_runtime.h>
#include <cuda_bf16.h>
#include <cstdint>

#define CI 128
#define CO 128
#define NE 4
#define MAXROWS (2048*128)
#define BM 128

// ---------------- scratch (__device__ globals; no dynamic alloc allowed) ----
__device__ int g_row_idx[NE][MAXROWS];
__device__ int g_count[NE];
// Pre-swizzled SMEM-image of W[e] (transposed to [N=CO rows, K=CI cols],
// K-major SW128 blocked layout), split into bf16 hi/lo.
__device__ __align__(16) unsigned char g_wimg_hi[NE][32768];
__device__ __align__(16) unsigned char g_wimg_lo[NE][32768];

// ---------------- small helpers ---------------------------------------------
__device__ __forceinline__ uint32_t smem_u32(const void* p) {
    uint32_t a;
    asm("{ .reg .u64 t; cvta.to.shared.u64 t, %1; cvt.u32.u64 %0, t; }"
        : "=r"(a) : "l"(p));
    return a;
}
__device__ __forceinline__ uint32_t swz(uint32_t off) {   // SW128: Swizzle<3,4,3>
    return off ^ ((off >> 3) & 0x70);
}

// SMEM descriptor: SW128, version=1(Blackwell), SBO=64, LBO=1 (K-major)
static __device__ __forceinline__ uint64_t make_desc(uint32_t addr) {
    const uint64_t BASE = (uint64_t(2) << 61) | (uint64_t(1) << 46) |
                          (uint64_t(64) << 32) | (uint64_t(1) << 16);
    return BASE | ((uint64_t)(addr >> 4) & 0x3FFF);
}

// idesc kind::f16: F32 accum(1<<4), a=BF16(1<<7), b=BF16(1<<10),
// N=128((128/8)<<17), M=128((128/16)<<24)
#define MMA_IDESC 0x8200490u

// Blocked-atom byte offset for element (row, col) in a [128 x 128] bf16 K-major
// SW128 tile: atoms of 8 rows x 64 cols (1024B), atom_offset = atom_row + atom_col*16.
__device__ __forceinline__ uint32_t tile_off_128r(uint32_t row, uint32_t col) {
    return ((row >> 3) + (col >> 6) * 16u) * 1024u + (row & 7u) * 128u + (col & 63u) * 2u;
}

// ---------------- bucketing / zero kernels ----------------------------------
__global__ void k_reset() {
    if (threadIdx.x < NE) g_count[threadIdx.x] = 0;
}

__global__ void k_scatter(const int* __restrict__ atom_numbers,
                          const int* __restrict__ atom_cases, int nrows) {
    int row = blockIdx.x * blockDim.x + threadIdx.x;
    bool valid = row < nrows;
    int an = valid ? atom_numbers[row] : -1234567;
    int c0 = __ldg(atom_cases + 0), c1 = __ldg(atom_cases + 1);
    int c2 = __ldg(atom_cases + 2), c3 = __ldg(atom_cases + 3);
    int e = -1;
    if (an == c0) e = 0;
    else if (an == c1) e = 1;
    else if (an == c2) e = 2;
    else if (an == c3) e = 3;

    unsigned lane = threadIdx.x & 31u;
#pragma unroll
    for (int ee = 0; ee < NE; ee++) {
        unsigned m = __ballot_sync(0xffffffffu, e == ee);
        if (e == ee) {
            int leader = __ffs(m) - 1;
            int base = 0;
            if ((int)lane == leader) base = atomicAdd(&g_count[ee], __popc(m));
            base = __shfl_sync(m, base, leader);
            int pos = base + __popc(m & ((1u << lane) - 1u));
            g_row_idx[ee][pos] = row;
        }
    }
}

__global__ void k_zero(float* __restrict__ out,
                       const int* __restrict__ atom_numbers,
                       const int* __restrict__ atom_cases, int nrows) {
    int i4 = blockIdx.x * blockDim.x + threadIdx.x;
    int total4 = nrows * (CO / 4);
    if (i4 >= total4) return;
    int row = i4 / (CO / 4);
    int an = __ldg(atom_numbers + row);
    bool matched = (an == __ldg(atom_cases + 0)) | (an == __ldg(atom_cases + 1)) |
                   (an == __ldg(atom_cases + 2)) | (an == __ldg(atom_cases + 3));
    if (!matched) ((float4*)out)[i4] = make_float4(0.f, 0.f, 0.f, 0.f);
}

// ---------------- W prep: fp32 [E][K][O] -> per-expert swizzled bf16 hi/lo images
__global__ void k_wprep(const float* __restrict__ W) {
    int e = blockIdx.x;
    const float* We = W + (size_t)e * CI * CO;
    for (int item = threadIdx.x; item < CO * 16; item += blockDim.x) {
        int o = item >> 4;        // B row (output channel) 0..127
        int kc = item & 15;       // 8-wide K chunk 0..15
        unsigned short h[8], l[8];
#pragma unroll
        for (int j = 0; j < 8; j++) {
            float f = We[(kc * 8 + j) * CO + o];   // transpose: B[o][k] = W[k][o]
            __nv_bfloat16 hb = __float2bfloat16_rn(f);
            float r = f - __bfloat162float(hb);
            __nv_bfloat16 lb = __float2bfloat16_rn(r);
            h[j] = __bfloat16_as_ushort(hb);
            l[j] = __bfloat16_as_ushort(lb);
        }
        uint32_t s = swz(tile_off_128r(o, kc * 8));
        uint4 vh = make_uint4((uint32_t)h[0] | ((uint32_t)h[1] << 16),
                              (uint32_t)h[2] | ((uint32_t)h[3] << 16),
                              (uint32_t)h[4] | ((uint32_t)h[5] << 16),
                              (uint32_t)h[6] | ((uint32_t)h[7] << 16));
        uint4 vl = make_uint4((uint32_t)l[0] | ((uint32_t)l[1] << 16),
                              (uint32_t)l[2] | ((uint32_t)l[3] << 16),
                              (uint32_t)l[4] | ((uint32_t)l[5] << 16),
                              (uint32_t)l[6] | ((uint32_t)l[7] << 16));
        *(uint4*)(g_wimg_hi[e] + s) = vh;
        *(uint4*)(g_wimg_lo[e] + s) = vl;
    }
}

// ---------------- grouped GEMM ----------------------------------------------
// Block: 128 gathered rows of one expert x CO=128, K=128.
// tcgen05 path (sm_103a only): D = A_hi*B_hi + A_lo*B_hi + A_hi*B_lo
// (bf16 split, fp32 TMEM accumulate).
// Non-103a compilation pass gets a correct fp32 SIMT fallback (the driver
// selects the exact-match sm_103a cubin at runtime; fallback exists so every
// gencode pass compiles and any PTX-JIT path stays correct).
#define OFF_A_HI 0u
#define OFF_A_LO 32768u
#define OFF_B_HI 65536u
#define OFF_B_LO 98304u
#define OFF_CTRL 131072u
#define SMEM_BYTES (131072 + 1024 + 1024)   // tiles + ctrl + align slack

__global__ void __launch_bounds__(256, 1)
k_gemm(const float* __restrict__ x, const float* __restrict__ W,
       const float* __restrict__ bias, float* __restrict__ out) {
    int e = blockIdx.y;
    int cnt = g_count[e];
    int m0 = blockIdx.x * BM;
    if (m0 >= cnt) return;
    int nr = min(BM, cnt - m0);
    int t = threadIdx.x;

#if defined(__CUDA_ARCH__) && !defined(__CUDA_ARCH_FEAT_SM103_ALL)
    // ---------------- fallback: fp32 SIMT (correct, slow; JIT-safety only) ---
    for (int idx = t; idx < nr * CO; idx += 256) {
        int m = idx >> 7, o = idx & 127;
        int grow = g_row_idx[e][m0 + m];
        const float* xr = x + (size_t)grow * CI;
        const float* wc = W + (size_t)e * CI * CO + o;
        float acc = bias[e * CO + o];
        for (int k = 0; k < CI; k++) acc += xr[k] * wc[(size_t)k * CO];
        out[(size_t)grow * CO + o] = fmaxf(acc, 0.f);
    }
#else
    // ---------------- tcgen05 path -------------------------------------------
    extern __shared__ unsigned char smraw[];
    uint32_t sraw = smem_u32(smraw);
    uint32_t sbase = (sraw + 1023u) & ~1023u;          // 1024-align for SW128 desc
    unsigned char* sm = smraw + (sbase - sraw);
    uint32_t s_ctrl = sbase + OFF_CTRL;                 // [0]=tmem ptr, [8]=mbar, [64..]=bias

    int wid = t >> 5, lane = t & 31;

    if (wid == 0) {
        asm volatile("tcgen05.alloc.cta_group::1.sync.aligned.shared::cta.b32 [%0], %1;"
                     :: "r"(s_ctrl), "r"(128u) : "memory");
        asm volatile("tcgen05.relinquish_alloc_permit.cta_group::1.sync.aligned;");
    }
    if (t == 0) {
        asm volatile("mbarrier.init.shared.b64 [%0], %1;"
                     :: "r"(s_ctrl + 8), "r"(1u) : "memory");
    }
    if (t < CO) ((float*)(sm + OFF_CTRL + 64))[t] = bias[e * CO + t];

    // Copy pre-swizzled W images (L2-resident after first wave): 2x 32KB
    {
        const uint4* gh = (const uint4*)g_wimg_hi[e];
        const uint4* gl = (const uint4*)g_wimg_lo[e];
        uint4* bh = (uint4*)(sm + OFF_B_HI);
        uint4* bl = (uint4*)(sm + OFF_B_LO);
#pragma unroll
        for (int i = 0; i < 8; i++) {
            bh[t + i * 256] = gh[t + i * 256];
            bl[t + i * 256] = gl[t + i * 256];
        }
    }

    // Gather + split-convert x rows: 2 threads per row (one 64-col half each)
    {
        int r = t >> 1, half = t & 1;
        bool val = r < nr;
        const float4* xr = nullptr;
        if (val) {
            int grow = __ldg(&g_row_idx[e][m0 + r]);
            xr = (const float4*)(x + (size_t)grow * CI + half * 64);
        }
        uint32_t rowoff = ((uint32_t)(r >> 3) + (uint32_t)half * 16u) * 1024u + (r & 7u) * 128u;
#pragma unroll
        for (int c8 = 0; c8 < 8; c8++) {
            uint4 vh = make_uint4(0, 0, 0, 0), vl = make_uint4(0, 0, 0, 0);
            if (val) {
                float4 f0 = xr[c8 * 2], f1 = xr[c8 * 2 + 1];
                float ff[8] = {f0.x, f0.y, f0.z, f0.w, f1.x, f1.y, f1.z, f1.w};
                uint32_t ph[4], pl[4];
#pragma unroll
                for (int j = 0; j < 4; j++) {
                    __nv_bfloat16 h0 = __float2bfloat16_rn(ff[2 * j]);
                    __nv_bfloat16 h1 = __float2bfloat16_rn(ff[2 * j + 1]);
                    __nv_bfloat16 l0 = __float2bfloat16_rn(ff[2 * j] - __bfloat162float(h0));
                    __nv_bfloat16 l1 = __float2bfloat16_rn(ff[2 * j + 1] - __bfloat162float(h1));
                    ph[j] = (uint32_t)__bfloat16_as_ushort(h0) |
                            ((uint32_t)__bfloat16_as_ushort(h1) << 16);
                    pl[j] = (uint32_t)__bfloat16_as_ushort(l0) |
                            ((uint32_t)__bfloat16_as_ushort(l1) << 16);
                }
                vh = make_uint4(ph[0], ph[1], ph[2], ph[3]);
                vl = make_uint4(pl[0], pl[1], pl[2], pl[3]);
            }
            uint32_t s = swz(rowoff + c8 * 16u);
            *(uint4*)(sm + OFF_A_HI + s) = vh;
            *(uint4*)(sm + OFF_A_LO + s) = vl;
        }
    }

    asm volatile("fence.proxy.async.shared::cta;" ::: "memory");
    __syncthreads();

    uint32_t tmem;
    asm volatile("ld.shared.b32 %0, [%1];" : "=r"(tmem) : "r"(s_ctrl));

    if (t == 0) {
        uint64_t dah = make_desc(sbase + OFF_A_HI);
        uint64_t dal = make_desc(sbase + OFF_A_LO);
        uint64_t dbh = make_desc(sbase + OFF_B_HI);
        uint64_t dbl = make_desc(sbase + OFF_B_LO);
        uint64_t ta[3] = {dah, dal, dah};
        uint64_t tb[3] = {dbh, dbh, dbl};
        uint32_t en = 0;
#pragma unroll
        for (int term = 0; term < 3; term++) {
#pragma unroll
            for (int k = 0; k < 8; k++) {
                // K16-step: +2 units within 64-col atom block, +1024 units per atom-col
                uint64_t off = (uint64_t)((k >> 2) * 1024 + (k & 3) * 2);
                asm volatile(
                    "{\n\t.reg .pred p;\n\t"
                    "setp.ne.u32 p, %4, 0;\n\t"
                    "tcgen05.mma.cta_group::1.kind::f16 [%0], %1, %2, %3, {%5, %5, %5, %5}, p;\n\t}"
                    :: "r"(tmem), "l"(ta[term] + off), "l"(tb[term] + off),
                       "r"(MMA_IDESC), "r"(en), "r"(0u) : "memory");
                en = 1;
            }
        }
        asm volatile(
            "tcgen05.commit.cta_group::1.mbarrier::arrive::one.shared::cluster.b64 [%0];"
            :: "r"(s_ctrl + 8) : "memory");
    }

    {
        uint32_t done = 0;
        while (!done) {
            asm volatile(
                "{\n\t.reg .pred p;\n\t"
                "mbarrier.try_wait.parity.acquire.cta.shared::cta.b64 p, [%1], %2, 0x989680;\n\t"
                "selp.b32 %0, 1, 0, p;\n\t}"
                : "=r"(done) : "r"(s_ctrl + 8), "r"(0u) : "memory");
        }
    }
    asm volatile("tcgen05.fence::after_thread_sync;" ::: "memory");

    // Epilogue: warps 0-3 read D (each its 32-lane subpartition), +bias, relu, scatter
    if (wid < 4) {
        int m = wid * 32 + lane;
        bool val = m < nr;
        int grow = val ? __ldg(&g_row_idx[e][m0 + m]) : 0;
        float* op = out + (size_t)grow * CO;
        const float* bsm = (const float*)(sm + OFF_CTRL + 64);
#pragma unroll
        for (int cb = 0; cb < 4; cb++) {
            uint32_t d[32];
            asm volatile(
                "tcgen05.ld.sync.aligned.32x32b.x32.b32 "
                "{%0, %1, %2, %3, %4, %5, %6, %7, "
                " %8, %9, %10, %11, %12, %13, %14, %15, "
                " %16, %17, %18, %19, %20, %21, %22, %23, "
                " %24, %25, %26, %27, %28, %29, %30, %31}, [%32];"
                : "=r"(d[0]),  "=r"(d[1]),  "=r"(d[2]),  "=r"(d[3]),
                  "=r"(d[4]),  "=r"(d[5]),  "=r"(d[6]),  "=r"(d[7]),
                  "=r"(d[8]),  "=r"(d[9]),  "=r"(d[10]), "=r"(d[11]),
                  "=r"(d[12]), "=r"(d[13]), "=r"(d[14]), "=r"(d[15]),
                  "=r"(d[16]), "=r"(d[17]), "=r"(d[18]), "=r"(d[19]),
                  "=r"(d[20]), "=r"(d[21]), "=r"(d[22]), "=r"(d[23]),
                  "=r"(d[24]), "=r"(d[25]), "=r"(d[26]), "=r"(d[27]),
                  "=r"(d[28]), "=r"(d[29]), "=r"(d[30]), "=r"(d[31])
                : "r"(tmem + cb * 32));
            asm volatile("tcgen05.wait::ld.sync.aligned;" ::: "memory");
#pragma unroll
            for (int j = 0; j < 32; j += 4) {
                float4 v;
                v.x = fmaxf(__uint_as_float(d[j + 0]) + bsm[cb * 32 + j + 0], 0.f);
                v.y = fmaxf(__uint_as_float(d[j + 1]) + bsm[cb * 32 + j + 1], 0.f);
                v.z = fmaxf(__uint_as_float(d[j + 2]) + bsm[cb * 32 + j + 2], 0.f);
                v.w = fmaxf(__uint_as_float(d[j + 3]) + bsm[cb * 32 + j + 3], 0.f);
                if (val) *(float4*)(op + cb * 32 + j) = v;
            }
        }
    }

    __syncthreads();
    if (t == 0) {
        asm volatile("mbarrier.inval.shared.b64 [%0];" :: "r"(s_ctrl + 8) : "memory");
    }
    if (wid == 0) {
        asm volatile("tcgen05.dealloc.cta_group::1.sync.aligned.b32 %0, %1;"
                     :: "r"(tmem), "r"(128u));
    }
#endif
}

// ---------------- launch -----------------------------------------------------
extern "C" void kernel_launch(void* const* d_in, const int* in_sizes, int n_in,
                              void* d_out, int out_size) {
    const float* x = (const float*)d_in[0];
    const int* atom_numbers = (const int*)d_in[1];
    const float* W = (const float*)d_in[2];
    const float* bias = (const float*)d_in[3];
    const int* atom_cases = (const int*)d_in[4];
    float* out = (float*)d_out;

    int nrows = in_sizes[1];  // B * A

    k_reset<<<1, 32>>>();
    k_scatter<<<(nrows + 255) / 256, 256>>>(atom_numbers, atom_cases, nrows);
    k_wprep<<<NE, 256>>>(W);

    int total4 = nrows * (CO / 4);
    k_zero<<<(total4 + 255) / 256, 256>>>(out, atom_numbers, atom_cases, nrows);

    cudaFuncSetAttribute(k_gemm, cudaFuncAttributeMaxDynamicSharedMemorySize, SMEM_BYTES);
    dim3 grid((nrows + BM - 1) / BM, NE);
    k_gemm<<<grid, 256, SMEM_BYTES>>>(x, W, bias, out);
}

// round 4
// speedup vs baseline: 1.6887x; 1.1602x over previous
#include <cuda_runtime.h>
#include <cuda_bf16.h>
#include <cstdint>

#define CI 128
#define CO 128
#define NE 4
#define NB 5               // 4 experts + 1 "unmatched" bucket
#define MAXROWS (2048*128)
#define BM 128
#define NCTA 152           // persistent grid (GB300: 152 SMs)

// ---------------- scratch (__device__ globals; no dynamic alloc allowed) ----
__device__ int g_row_idx[NB][MAXROWS];
__device__ int g_count[NB];
// Pre-swizzled SMEM-image of W[e] (transposed to [N=CO rows, K=CI cols],
// K-major SW128 blocked layout), split into bf16 hi/lo.
__device__ __align__(16) unsigned char g_wimg_hi[NE][32768];
__device__ __align__(16) unsigned char g_wimg_lo[NE][32768];

// ---------------- small helpers ---------------------------------------------
__device__ __forceinline__ uint32_t smem_u32(const void* p) {
    uint32_t a;
    asm("{ .reg .u64 t; cvta.to.shared.u64 t, %1; cvt.u32.u64 %0, t; }"
        : "=r"(a) : "l"(p));
    return a;
}
__device__ __forceinline__ uint32_t swz(uint32_t off) {   // SW128: Swizzle<3,4,3>
    return off ^ ((off >> 3) & 0x70);
}

// SMEM descriptor: SW128, version=1(Blackwell), SBO=64, LBO=1 (K-major)
static __device__ __forceinline__ uint64_t make_desc(uint32_t addr) {
    const uint64_t BASE = (uint64_t(2) << 61) | (uint64_t(1) << 46) |
                          (uint64_t(64) << 32) | (uint64_t(1) << 16);
    return BASE | ((uint64_t)(addr >> 4) & 0x3FFF);
}

// idesc kind::f16: F32 accum(1<<4), a=BF16(1<<7), b=BF16(1<<10),
// N=128((128/8)<<17), M=128((128/16)<<24)
#define MMA_IDESC 0x8200490u

// Blocked-atom byte offset for element (row, col) in a [128 x 128] bf16 K-major
// SW128 tile: atoms of 8 rows x 64 cols (1024B), atom_offset = atom_row + atom_col*16.
__device__ __forceinline__ uint32_t tile_off_128r(uint32_t row, uint32_t col) {
    return ((row >> 3) + (col >> 6) * 16u) * 1024u + (row & 7u) * 128u + (col & 63u) * 2u;
}

// ---------------- bucketing / zero kernels ----------------------------------
__global__ void k_reset() {
    if (threadIdx.x < NB) g_count[threadIdx.x] = 0;
}

__global__ void k_scatter(const int* __restrict__ atom_numbers,
                          const int* __restrict__ atom_cases, int nrows) {
    int row = blockIdx.x * blockDim.x + threadIdx.x;
    bool valid = row < nrows;
    int an = valid ? atom_numbers[row] : -1234567;
    int c0 = __ldg(atom_cases + 0), c1 = __ldg(atom_cases + 1);
    int c2 = __ldg(atom_cases + 2), c3 = __ldg(atom_cases + 3);
    int e = 4;                       // bucket 4 = unmatched (needs zero output)
    if (an == c0) e = 0;
    else if (an == c1) e = 1;
    else if (an == c2) e = 2;
    else if (an == c3) e = 3;
    if (!valid) e = -1;

    unsigned lane = threadIdx.x & 31u;
#pragma unroll
    for (int ee = 0; ee < NB; ee++) {
        unsigned m = __ballot_sync(0xffffffffu, e == ee);
        if (e == ee) {
            int leader = __ffs(m) - 1;
            int base = 0;
            if ((int)lane == leader) base = atomicAdd(&g_count[ee], __popc(m));
            base = __shfl_sync(m, base, leader);
            int pos = base + __popc(m & ((1u << lane) - 1u));
            g_row_idx[ee][pos] = row;
        }
    }
}

// Zero unmatched rows from the gathered list: one float4 per thread,
// one (L2-broadcast) index load per warp, zero divergence, pure write stream.
__global__ void k_zero(float* __restrict__ out) {
    int cnt4 = g_count[4] * (CO / 4);
    int stride = gridDim.x * blockDim.x;
    for (int i = blockIdx.x * blockDim.x + threadIdx.x; i < cnt4; i += stride) {
        int r = i >> 5;                       // 32 float4 per row
        int grow = __ldg(&g_row_idx[4][r]);
        ((float4*)out)[(size_t)grow * (CO / 4) + (i & 31)] =
            make_float4(0.f, 0.f, 0.f, 0.f);
    }
}

// ---------------- W prep: fp32 [E][K][O] -> per-expert swizzled bf16 hi/lo images
// Stage W[e] in smem with coalesced global reads, then build swizzled images.
__global__ void k_wprep(const float* __restrict__ W) {
    extern __shared__ float ws[];             // 64KB: W[e] staged
    int e = blockIdx.x;
    const float* We = W + (size_t)e * CI * CO;
    for (int i = threadIdx.x; i < CI * CO; i += blockDim.x) ws[i] = We[i];
    __syncthreads();

    for (int item = threadIdx.x; item < CO * 16; item += blockDim.x) {
        int o = item >> 4;        // B row (output channel) 0..127
        int kc = item & 15;       // 8-wide K chunk 0..15
        unsigned short h[8], l[8];
#pragma unroll
        for (int j = 0; j < 8; j++) {
            float f = ws[(kc * 8 + j) * CO + o];   // transpose: B[o][k] = W[k][o]
            __nv_bfloat16 hb = __float2bfloat16_rn(f);
            float r = f - __bfloat162float(hb);
            __nv_bfloat16 lb = __float2bfloat16_rn(r);
            h[j] = __bfloat16_as_ushort(hb);
            l[j] = __bfloat16_as_ushort(lb);
        }
        uint32_t s = swz(tile_off_128r(o, kc * 8));
        uint4 vh = make_uint4((uint32_t)h[0] | ((uint32_t)h[1] << 16),
                              (uint32_t)h[2] | ((uint32_t)h[3] << 16),
                              (uint32_t)h[4] | ((uint32_t)h[5] << 16),
                              (uint32_t)h[6] | ((uint32_t)h[7] << 16));
        uint4 vl = make_uint4((uint32_t)l[0] | ((uint32_t)l[1] << 16),
                              (uint32_t)l[2] | ((uint32_t)l[3] << 16),
                              (uint32_t)l[4] | ((uint32_t)l[5] << 16),
                              (uint32_t)l[6] | ((uint32_t)l[7] << 16));
        *(uint4*)((unsigned char*)g_wimg_hi[e] + s) = vh;
        *(uint4*)((unsigned char*)g_wimg_lo[e] + s) = vl;
    }
}

// ---------------- persistent grouped GEMM ------------------------------------
// 152 persistent CTAs; static contiguous tile partition from g_count prefix.
// Per tile: 128 gathered rows of one expert x CO=128, K=128.
// tcgen05: D = A_hi*B_hi + A_lo*B_hi + A_hi*B_lo (bf16 split, fp32 TMEM accum).
#define OFF_A_HI 0u
#define OFF_A_LO 32768u
#define OFF_B_HI 65536u
#define OFF_B_LO 98304u
#define OFF_CTRL 131072u
#define SMEM_BYTES (131072 + 1024 + 1024)

__global__ void __launch_bounds__(256, 1)
k_gemm(const float* __restrict__ x, const float* __restrict__ W,
       const float* __restrict__ bias, float* __restrict__ out) {
    int t = threadIdx.x;

    // Tile partition (uniform across threads)
    int c[NE], tiles[NE], pfx[NE + 1];
    pfx[0] = 0;
#pragma unroll
    for (int e = 0; e < NE; e++) {
        c[e] = g_count[e];
        tiles[e] = (c[e] + BM - 1) >> 7;
        pfx[e + 1] = pfx[e] + tiles[e];
    }
    int total = pfx[NE];
    int begin = (int)((long long)total * blockIdx.x / gridDim.x);
    int end   = (int)((long long)total * (blockIdx.x + 1) / gridDim.x);
    if (begin >= end) return;

#if defined(__CUDA_ARCH__) && !defined(__CUDA_ARCH_FEAT_SM103_ALL)
    // ---------------- fallback: fp32 SIMT (JIT-safety only) ------------------
    for (int tile = begin; tile < end; tile++) {
        int e = 0;
        while (tile >= pfx[e + 1]) e++;
        int m0 = (tile - pfx[e]) * BM;
        int nr = min(BM, c[e] - m0);
        for (int idx = t; idx < nr * CO; idx += 256) {
            int m = idx >> 7, o = idx & 127;
            int grow = g_row_idx[e][m0 + m];
            const float* xr = x + (size_t)grow * CI;
            const float* wc = W + (size_t)e * CI * CO + o;
            float acc = bias[e * CO + o];
            for (int k = 0; k < CI; k++) acc += xr[k] * wc[(size_t)k * CO];
            out[(size_t)grow * CO + o] = fmaxf(acc, 0.f);
        }
    }
#else
    // ---------------- tcgen05 path -------------------------------------------
    extern __shared__ unsigned char smraw[];
    uint32_t sraw = smem_u32(smraw);
    uint32_t sbase = (sraw + 1023u) & ~1023u;          // 1024-align for SW128
    unsigned char* sm = smraw + (sbase - sraw);
    uint32_t s_ctrl = sbase + OFF_CTRL;                 // [0]=tmem, [8]=mbar, [64..]=bias

    int wid = t >> 5, lane = t & 31;

    if (wid == 0) {
        asm volatile("tcgen05.alloc.cta_group::1.sync.aligned.shared::cta.b32 [%0], %1;"
                     :: "r"(s_ctrl), "r"(128u) : "memory");
        asm volatile("tcgen05.relinquish_alloc_permit.cta_group::1.sync.aligned;");
    }
    if (t == 0) {
        asm volatile("mbarrier.init.shared.b64 [%0], %1;"
                     :: "r"(s_ctrl + 8), "r"(1u) : "memory");
    }
    __syncthreads();
    uint32_t tmem;
    asm volatile("ld.shared.b32 %0, [%1];" : "=r"(tmem) : "r"(s_ctrl));

    uint64_t dah = make_desc(sbase + OFF_A_HI);
    uint64_t dal = make_desc(sbase + OFF_A_LO);
    uint64_t dbh = make_desc(sbase + OFF_B_HI);
    uint64_t dbl = make_desc(sbase + OFF_B_LO);

    int cur_e = -1;
    for (int tile = begin; tile < end; tile++) {
        int e = 0;
        while (tile >= pfx[e + 1]) e++;
        int m0 = (tile - pfx[e]) * BM;
        int nr = min(BM, c[e] - m0);
        int par = (tile - begin) & 1;

        // W images + bias: only on expert change (L2-resident, 64KB + 512B)
        if (e != cur_e) {
            cur_e = e;
            const uint4* gh = (const uint4*)g_wimg_hi[e];
            const uint4* gl = (const uint4*)g_wimg_lo[e];
            uint4* bh = (uint4*)(sm + OFF_B_HI);
            uint4* bl = (uint4*)(sm + OFF_B_LO);
#pragma unroll
            for (int i = 0; i < 8; i++) {
                bh[t + i * 256] = gh[t + i * 256];
                bl[t + i * 256] = gl[t + i * 256];
            }
            if (t < CO) ((float*)(sm + OFF_CTRL + 64))[t] = bias[e * CO + t];
        }

        // Gather + split-convert x rows: 2 threads per row (one 64-col half)
        {
            int r = t >> 1, half = t & 1;
            bool val = r < nr;
            const float4* xr = nullptr;
            if (val) {
                int grow = __ldg(&g_row_idx[e][m0 + r]);
                xr = (const float4*)(x + (size_t)grow * CI + half * 64);
            }
            uint32_t rowoff = ((uint32_t)(r >> 3) + (uint32_t)half * 16u) * 1024u +
                              (r & 7u) * 128u;
#pragma unroll
            for (int c8 = 0; c8 < 8; c8++) {
                uint4 vh = make_uint4(0, 0, 0, 0), vl = make_uint4(0, 0, 0, 0);
                if (val) {
                    float4 f0 = xr[c8 * 2], f1 = xr[c8 * 2 + 1];
                    float ff[8] = {f0.x, f0.y, f0.z, f0.w, f1.x, f1.y, f1.z, f1.w};
                    uint32_t ph[4], pl[4];
#pragma unroll
                    for (int j = 0; j < 4; j++) {
                        __nv_bfloat16 h0 = __float2bfloat16_rn(ff[2 * j]);
                        __nv_bfloat16 h1 = __float2bfloat16_rn(ff[2 * j + 1]);
                        __nv_bfloat16 l0 = __float2bfloat16_rn(ff[2 * j] - __bfloat162float(h0));
                        __nv_bfloat16 l1 = __float2bfloat16_rn(ff[2 * j + 1] - __bfloat162float(h1));
                        ph[j] = (uint32_t)__bfloat16_as_ushort(h0) |
                                ((uint32_t)__bfloat16_as_ushort(h1) << 16);
                        pl[j] = (uint32_t)__bfloat16_as_ushort(l0) |
                                ((uint32_t)__bfloat16_as_ushort(l1) << 16);
                    }
                    vh = make_uint4(ph[0], ph[1], ph[2], ph[3]);
                    vl = make_uint4(pl[0], pl[1], pl[2], pl[3]);
                }
                uint32_t s = swz(rowoff + c8 * 16u);
                *(uint4*)(sm + OFF_A_HI + s) = vh;
                *(uint4*)(sm + OFF_A_LO + s) = vl;
            }
        }

        asm volatile("fence.proxy.async.shared::cta;" ::: "memory");
        __syncthreads();

        if (t == 0) {
            uint64_t ta[3] = {dah, dal, dah};
            uint64_t tb[3] = {dbh, dbh, dbl};
            uint32_t en = 0;
#pragma unroll
            for (int term = 0; term < 3; term++) {
#pragma unroll
                for (int k = 0; k < 8; k++) {
                    uint64_t off = (uint64_t)((k >> 2) * 1024 + (k & 3) * 2);
                    asm volatile(
                        "{\n\t.reg .pred p;\n\t"
                        "setp.ne.u32 p, %4, 0;\n\t"
                        "tcgen05.mma.cta_group::1.kind::f16 [%0], %1, %2, %3, {%5, %5, %5, %5}, p;\n\t}"
                        :: "r"(tmem), "l"(ta[term] + off), "l"(tb[term] + off),
                           "r"(MMA_IDESC), "r"(en), "r"(0u) : "memory");
                    en = 1;
                }
            }
            asm volatile(
                "tcgen05.commit.cta_group::1.mbarrier::arrive::one.shared::cluster.b64 [%0];"
                :: "r"(s_ctrl + 8) : "memory");
        }

        {
            uint32_t done = 0;
            while (!done) {
                asm volatile(
                    "{\n\t.reg .pred p;\n\t"
                    "mbarrier.try_wait.parity.acquire.cta.shared::cta.b64 p, [%1], %2, 0x989680;\n\t"
                    "selp.b32 %0, 1, 0, p;\n\t}"
                    : "=r"(done) : "r"(s_ctrl + 8), "r"((uint32_t)par) : "memory");
            }
        }
        asm volatile("tcgen05.fence::after_thread_sync;" ::: "memory");

        // Epilogue: warps 0-3 read D, +bias, relu, scatter-store
        if (wid < 4) {
            int m = wid * 32 + lane;
            bool val = m < nr;
            int grow = val ? __ldg(&g_row_idx[e][m0 + m]) : 0;
            float* op = out + (size_t)grow * CO;
            const float* bsm = (const float*)(sm + OFF_CTRL + 64);
#pragma unroll
            for (int cb = 0; cb < 4; cb++) {
                uint32_t d[32];
                asm volatile(
                    "tcgen05.ld.sync.aligned.32x32b.x32.b32 "
                    "{%0, %1, %2, %3, %4, %5, %6, %7, "
                    " %8, %9, %10, %11, %12, %13, %14, %15, "
                    " %16, %17, %18, %19, %20, %21, %22, %23, "
                    " %24, %25, %26, %27, %28, %29, %30, %31}, [%32];"
                    : "=r"(d[0]),  "=r"(d[1]),  "=r"(d[2]),  "=r"(d[3]),
                      "=r"(d[4]),  "=r"(d[5]),  "=r"(d[6]),  "=r"(d[7]),
                      "=r"(d[8]),  "=r"(d[9]),  "=r"(d[10]), "=r"(d[11]),
                      "=r"(d[12]), "=r"(d[13]), "=r"(d[14]), "=r"(d[15]),
                      "=r"(d[16]), "=r"(d[17]), "=r"(d[18]), "=r"(d[19]),
                      "=r"(d[20]), "=r"(d[21]), "=r"(d[22]), "=r"(d[23]),
                      "=r"(d[24]), "=r"(d[25]), "=r"(d[26]), "=r"(d[27]),
                      "=r"(d[28]), "=r"(d[29]), "=r"(d[30]), "=r"(d[31])
                    : "r"(tmem + cb * 32));
                asm volatile("tcgen05.wait::ld.sync.aligned;" ::: "memory");
#pragma unroll
                for (int j = 0; j < 32; j += 4) {
                    float4 v;
                    v.x = fmaxf(__uint_as_float(d[j + 0]) + bsm[cb * 32 + j + 0], 0.f);
                    v.y = fmaxf(__uint_as_float(d[j + 1]) + bsm[cb * 32 + j + 1], 0.f);
                    v.z = fmaxf(__uint_as_float(d[j + 2]) + bsm[cb * 32 + j + 2], 0.f);
                    v.w = fmaxf(__uint_as_float(d[j + 3]) + bsm[cb * 32 + j + 3], 0.f);
                    if (val) *(float4*)(op + cb * 32 + j) = v;
                }
            }
            asm volatile("tcgen05.fence::before_thread_sync;" ::: "memory");
        }
        __syncthreads();   // epilogue done before next tile overwrites A/B/D
    }

    if (t == 0) {
        asm volatile("mbarrier.inval.shared.b64 [%0];" :: "r"(s_ctrl + 8) : "memory");
    }
    __syncthreads();
    if (wid == 0) {
        asm volatile("tcgen05.dealloc.cta_group::1.sync.aligned.b32 %0, %1;"
                     :: "r"(tmem), "r"(128u));
    }
#endif
}

// ---------------- launch -----------------------------------------------------
extern "C" void kernel_launch(void* const* d_in, const int* in_sizes, int n_in,
                              void* d_out, int out_size) {
    const float* x = (const float*)d_in[0];
    const int* atom_numbers = (const int*)d_in[1];
    const float* W = (const float*)d_in[2];
    const float* bias = (const float*)d_in[3];
    const int* atom_cases = (const int*)d_in[4];
    float* out = (float*)d_out;

    int nrows = in_sizes[1];  // B * A

    k_reset<<<1, 32>>>();
    k_scatter<<<(nrows + 255) / 256, 256>>>(atom_numbers, atom_cases, nrows);

    cudaFuncSetAttribute(k_wprep, cudaFuncAttributeMaxDynamicSharedMemorySize, 65536);
    k_wprep<<<NE, 256, 65536>>>(W);

    k_zero<<<2048, 256>>>(out);

    cudaFuncSetAttribute(k_gemm, cudaFuncAttributeMaxDynamicSharedMemorySize, SMEM_BYTES);
    k_gemm<<<NCTA, 256, SMEM_BYTES>>>(x, W, bias, out);
}

// round 5
// speedup vs baseline: 2.1206x; 1.2558x over previous
#include <cuda_runtime.h>
#include <cuda_bf16.h>
#include <cstdint>

#define CI 128
#define CO 128
#define NE 4
#define NB 5               // 4 experts + 1 "unmatched" bucket
#define MAXROWS (2048*128)
#define BM 128
#define NCTA 152           // persistent grid (GB300: 152 SMs)

// ---------------- scratch (__device__ globals; no dynamic alloc allowed) ----
__device__ int g_row_idx[NB][MAXROWS];
__device__ int g_count[NB];
// Pre-swizzled SMEM-image of W[e] (transposed to [N=CO rows, K=CI cols],
// K-major SW128 blocked layout), split into bf16 hi/lo.
__device__ __align__(16) unsigned char g_wimg_hi[NE][32768];
__device__ __align__(16) unsigned char g_wimg_lo[NE][32768];

// ---------------- small helpers ---------------------------------------------
__device__ __forceinline__ uint32_t smem_u32(const void* p) {
    uint32_t a;
    asm("{ .reg .u64 t; cvta.to.shared.u64 t, %1; cvt.u32.u64 %0, t; }"
        : "=r"(a) : "l"(p));
    return a;
}
__device__ __forceinline__ uint32_t swz(uint32_t off) {   // SW128: Swizzle<3,4,3>
    return off ^ ((off >> 3) & 0x70);
}

// pairwise fp32 -> bf16 hi/lo split: h packs {lo=cvt(a), hi=cvt(b)},
// l packs residuals likewise. (cvt.rn.bf16x2.f32 %0,hi_src,lo_src)
__device__ __forceinline__ void split2(uint32_t& h, uint32_t& l, float a, float b) {
    asm("cvt.rn.bf16x2.f32 %0, %1, %2;" : "=r"(h) : "f"(b), "f"(a));
    float ra = a - __uint_as_float(h << 16);
    float rb = b - __uint_as_float(h & 0xffff0000u);
    asm("cvt.rn.bf16x2.f32 %0, %1, %2;" : "=r"(l) : "f"(rb), "f"(ra));
}

// SMEM descriptor: SW128, version=1(Blackwell), SBO=64, LBO=1 (K-major)
static __device__ __forceinline__ uint64_t make_desc(uint32_t addr) {
    const uint64_t BASE = (uint64_t(2) << 61) | (uint64_t(1) << 46) |
                          (uint64_t(64) << 32) | (uint64_t(1) << 16);
    return BASE | ((uint64_t)(addr >> 4) & 0x3FFF);
}

// idesc kind::f16: F32 accum(1<<4), a=BF16(1<<7), b=BF16(1<<10),
// N=128((128/8)<<17), M=128((128/16)<<24)
#define MMA_IDESC 0x8200490u

// Blocked-atom byte offset for element (row, col) in a [128 x 128] bf16 K-major
// SW128 tile: atoms of 8 rows x 64 cols (1024B), atom_offset = atom_row + atom_col*16.
__device__ __forceinline__ uint32_t tile_off_128r(uint32_t row, uint32_t col) {
    return ((row >> 3) + (col >> 6) * 16u) * 1024u + (row & 7u) * 128u + (col & 63u) * 2u;
}

// ---------------- bucketing -------------------------------------------------
__global__ void k_reset() {
    if (threadIdx.x < NB) g_count[threadIdx.x] = 0;
}

// Block-aggregated bucketing: 1024 threads/block, one atomic per bucket per
// block (1280 total vs 8K+ same-address leader atomics before).
__global__ void __launch_bounds__(1024)
k_scatter(const int* __restrict__ atom_numbers,
          const int* __restrict__ atom_cases, int nrows) {
    __shared__ int wcnt[NB][32];
    __shared__ int sbase[NB];
    int t = threadIdx.x, w = t >> 5, lane = t & 31;
    int row = blockIdx.x * 1024 + t;
    bool valid = row < nrows;
    int an = valid ? atom_numbers[row] : -1234567;
    int c0 = __ldg(atom_cases + 0), c1 = __ldg(atom_cases + 1);
    int c2 = __ldg(atom_cases + 2), c3 = __ldg(atom_cases + 3);
    int e = 4;                       // bucket 4 = unmatched (needs zero output)
    if (an == c0) e = 0;
    else if (an == c1) e = 1;
    else if (an == c2) e = 2;
    else if (an == c3) e = 3;
    if (!valid) e = -1;

    int myrank = 0;
#pragma unroll
    for (int b = 0; b < NB; b++) {
        unsigned m = __ballot_sync(0xffffffffu, e == b);
        if (e == b) myrank = __popc(m & ((1u << lane) - 1u));
        if (lane == 0) wcnt[b][w] = __popc(m);
    }
    __syncthreads();
    if (t < NB) {
        int s = 0;
#pragma unroll
        for (int i = 0; i < 32; i++) { int v = wcnt[t][i]; wcnt[t][i] = s; s += v; }
        sbase[t] = s ? atomicAdd(&g_count[t], s) : 0;
    }
    __syncthreads();
    if (e >= 0) g_row_idx[e][sbase[e] + wcnt[e][w] + myrank] = row;
}

// ---------------- W prep: fp32 [E][K][O] -> per-expert swizzled bf16 hi/lo images
__global__ void k_wprep(const float* __restrict__ W) {
    extern __shared__ float ws[];             // 64KB: W[e] staged
    int e = blockIdx.x;
    const float* We = W + (size_t)e * CI * CO;
    for (int i = threadIdx.x; i < CI * CO; i += blockDim.x) ws[i] = We[i];
    __syncthreads();

    for (int item = threadIdx.x; item < CO * 16; item += blockDim.x) {
        int o = item >> 4;        // B row (output channel)
        int kc = item & 15;       // 8-wide K chunk
        uint32_t ph[4], pl[4];
#pragma unroll
        for (int j = 0; j < 4; j++) {
            float a = ws[(kc * 8 + 2 * j) * CO + o];
            float b = ws[(kc * 8 + 2 * j + 1) * CO + o];
            split2(ph[j], pl[j], a, b);
        }
        uint32_t s = swz(tile_off_128r(o, kc * 8));
        *(uint4*)((unsigned char*)g_wimg_hi[e] + s) = make_uint4(ph[0], ph[1], ph[2], ph[3]);
        *(uint4*)((unsigned char*)g_wimg_lo[e] + s) = make_uint4(pl[0], pl[1], pl[2], pl[3]);
    }
}

// ---------------- persistent pipelined grouped GEMM ---------------------------
// Double-buffered A in smem, double-buffered D in TMEM, two mbarriers.
// Per-iteration: gather A(t) -> sync -> issue MMA(t) -> wait(t-1)/epilogue(t-1).
// tcgen05: D = A_hi*B_hi + A_lo*B_hi + A_hi*B_lo (bf16 split, fp32 TMEM accum).
#define OFF_A(buf)  ((buf) * 65536u)            // A_hi at +0, A_lo at +32768
#define OFF_B_HI 131072u
#define OFF_B_LO 163840u
#define OFF_CTRL 196608u
#define SMEM_BYTES (196608 + 1024 + 1024)

__global__ void __launch_bounds__(256, 1)
k_gemm(const float* __restrict__ x, const float* __restrict__ W,
       const float* __restrict__ bias, float* __restrict__ out) {
    int t = threadIdx.x;

    // Tile partition (uniform across threads)
    int c[NE], pfx[NE + 1];
    pfx[0] = 0;
#pragma unroll
    for (int e = 0; e < NE; e++) {
        c[e] = g_count[e];
        pfx[e + 1] = pfx[e] + ((c[e] + BM - 1) >> 7);
    }
    int total = pfx[NE];
    int begin = (int)((long long)total * blockIdx.x / gridDim.x);
    int end   = (int)((long long)total * (blockIdx.x + 1) / gridDim.x);

    // Bucket-4 (unmatched) zero slice for this CTA
    int cnt4 = g_count[4];
    int z0 = (int)((long long)cnt4 * blockIdx.x / gridDim.x);
    int z1 = (int)((long long)cnt4 * (blockIdx.x + 1) / gridDim.x);

#if defined(__CUDA_ARCH__) && !defined(__CUDA_ARCH_FEAT_SM103_ALL)
    // ---------------- fallback: fp32 SIMT (JIT-safety only) ------------------
    for (int tile = begin; tile < end; tile++) {
        int e = 0;
        while (tile >= pfx[e + 1]) e++;
        int m0 = (tile - pfx[e]) * BM;
        int nr = min(BM, c[e] - m0);
        for (int idx = t; idx < nr * CO; idx += 256) {
            int m = idx >> 7, o = idx & 127;
            int grow = g_row_idx[e][m0 + m];
            const float* xr = x + (size_t)grow * CI;
            const float* wc = W + (size_t)e * CI * CO + o;
            float acc = bias[e * CO + o];
            for (int k = 0; k < CI; k++) acc += xr[k] * wc[(size_t)k * CO];
            out[(size_t)grow * CO + o] = fmaxf(acc, 0.f);
        }
    }
    for (int i = z0 * 32 + t; i < z1 * 32; i += 256) {
        int grow = g_row_idx[4][i >> 5];
        ((float4*)out)[(size_t)grow * 32 + (i & 31)] = make_float4(0.f, 0.f, 0.f, 0.f);
    }
#else
    // ---------------- tcgen05 path -------------------------------------------
    extern __shared__ unsigned char smraw[];
    uint32_t sraw = smem_u32(smraw);
    uint32_t sbase = (sraw + 1023u) & ~1023u;          // 1024-align for SW128
    unsigned char* sm = smraw + (sbase - sraw);
    uint32_t s_ctrl = sbase + OFF_CTRL;   // [0]=tmem, [8],[16]=mbars, [64..]=bias

    int wid = t >> 5, lane = t & 31;

    if (wid == 0) {
        asm volatile("tcgen05.alloc.cta_group::1.sync.aligned.shared::cta.b32 [%0], %1;"
                     :: "r"(s_ctrl), "r"(256u) : "memory");
        asm volatile("tcgen05.relinquish_alloc_permit.cta_group::1.sync.aligned;");
    }
    if (t == 0) {
        asm volatile("mbarrier.init.shared.b64 [%0], %1;"
                     :: "r"(s_ctrl + 8), "r"(1u) : "memory");
        asm volatile("mbarrier.init.shared.b64 [%0], %1;"
                     :: "r"(s_ctrl + 16), "r"(1u) : "memory");
    }
    __syncthreads();
    uint32_t tmem;
    asm volatile("ld.shared.b32 %0, [%1];" : "=r"(tmem) : "r"(s_ctrl));

    uint64_t dbh = make_desc(sbase + OFF_B_HI);
    uint64_t dbl = make_desc(sbase + OFF_B_LO);

    // pending-tile state
    bool pend = false;
    int pend_m0 = 0, pend_nr = 0, pend_buf = 0, pend_par = 0, pend_e = 0;

    // epilogue: warps 0-3 read D[dbuf], +bias, relu, scatter-store
    auto epilogue = [&](int em0, int enr, int ebuf, int ee) {
        if (wid < 4) {
            int m = wid * 32 + lane;
            bool val = m < enr;
            int grow = val ? __ldg(&g_row_idx[ee][em0 + m]) : 0;
            float* op = out + (size_t)grow * CO;
            const float* bsm = (const float*)(sm + OFF_CTRL + 64);
            uint32_t td = tmem + (uint32_t)ebuf * 128u;
#pragma unroll
            for (int cb = 0; cb < 4; cb++) {
                uint32_t d[32];
                asm volatile(
                    "tcgen05.ld.sync.aligned.32x32b.x32.b32 "
                    "{%0, %1, %2, %3, %4, %5, %6, %7, "
                    " %8, %9, %10, %11, %12, %13, %14, %15, "
                    " %16, %17, %18, %19, %20, %21, %22, %23, "
                    " %24, %25, %26, %27, %28, %29, %30, %31}, [%32];"
                    : "=r"(d[0]),  "=r"(d[1]),  "=r"(d[2]),  "=r"(d[3]),
                      "=r"(d[4]),  "=r"(d[5]),  "=r"(d[6]),  "=r"(d[7]),
                      "=r"(d[8]),  "=r"(d[9]),  "=r"(d[10]), "=r"(d[11]),
                      "=r"(d[12]), "=r"(d[13]), "=r"(d[14]), "=r"(d[15]),
                      "=r"(d[16]), "=r"(d[17]), "=r"(d[18]), "=r"(d[19]),
                      "=r"(d[20]), "=r"(d[21]), "=r"(d[22]), "=r"(d[23]),
                      "=r"(d[24]), "=r"(d[25]), "=r"(d[26]), "=r"(d[27]),
                      "=r"(d[28]), "=r"(d[29]), "=r"(d[30]), "=r"(d[31])
                    : "r"(td + cb * 32));
                asm volatile("tcgen05.wait::ld.sync.aligned;" ::: "memory");
#pragma unroll
                for (int j = 0; j < 32; j += 4) {
                    float4 v;
                    v.x = fmaxf(__uint_as_float(d[j + 0]) + bsm[cb * 32 + j + 0], 0.f);
                    v.y = fmaxf(__uint_as_float(d[j + 1]) + bsm[cb * 32 + j + 1], 0.f);
                    v.z = fmaxf(__uint_as_float(d[j + 2]) + bsm[cb * 32 + j + 2], 0.f);
                    v.w = fmaxf(__uint_as_float(d[j + 3]) + bsm[cb * 32 + j + 3], 0.f);
                    if (val) *(float4*)(op + cb * 32 + j) = v;
                }
            }
        }
    };
    auto wait_pend = [&]() {
        uint32_t mb = s_ctrl + 8 + 8 * (uint32_t)pend_buf;
        uint32_t done = 0;
        while (!done) {
            asm volatile(
                "{\n\t.reg .pred p;\n\t"
                "mbarrier.try_wait.parity.acquire.cta.shared::cta.b64 p, [%1], %2, 0x989680;\n\t"
                "selp.b32 %0, 1, 0, p;\n\t}"
                : "=r"(done) : "r"(mb), "r"((uint32_t)pend_par) : "memory");
        }
        asm volatile("tcgen05.fence::after_thread_sync;" ::: "memory");
    };

    int cur_e = -1;
    for (int tile = begin; tile < end; tile++) {
        int e = 0;
        while (tile >= pfx[e + 1]) e++;
        int m0 = (tile - pfx[e]) * BM;
        int nr = min(BM, c[e] - m0);
        int rel = tile - begin;
        int buf = rel & 1;

        // Expert change: drain pending MMA (it reads B), then reload B + bias
        if (e != cur_e) {
            if (pend) { wait_pend(); epilogue(pend_m0, pend_nr, pend_buf, pend_e); pend = false; }
            const uint4* gh = (const uint4*)g_wimg_hi[e];
            const uint4* gl = (const uint4*)g_wimg_lo[e];
            uint4* bh = (uint4*)(sm + OFF_B_HI);
            uint4* bl = (uint4*)(sm + OFF_B_LO);
#pragma unroll
            for (int i = 0; i < 8; i++) {
                bh[t + i * 256] = gh[t + i * 256];
                bl[t + i * 256] = gl[t + i * 256];
            }
            if (t < CO) ((float*)(sm + OFF_CTRL + 64))[t] = bias[e * CO + t];
            cur_e = e;
        }

        // Gather + split-convert x rows into A[buf]: 2 threads per row
        {
            int r = t >> 1, half = t & 1;
            bool val = r < nr;
            const float4* xr = nullptr;
            if (val) {
                int grow = __ldg(&g_row_idx[e][m0 + r]);
                xr = (const float4*)(x + (size_t)grow * CI + half * 64);
            }
            uint32_t rowoff = ((uint32_t)(r >> 3) + (uint32_t)half * 16u) * 1024u +
                              (r & 7u) * 128u;
            unsigned char* ah = sm + OFF_A(buf);
            unsigned char* al = ah + 32768;
#pragma unroll
            for (int c8 = 0; c8 < 8; c8++) {
                uint4 vh = make_uint4(0, 0, 0, 0), vl = make_uint4(0, 0, 0, 0);
                if (val) {
                    float4 f0 = xr[c8 * 2], f1 = xr[c8 * 2 + 1];
                    split2(vh.x, vl.x, f0.x, f0.y);
                    split2(vh.y, vl.y, f0.z, f0.w);
                    split2(vh.z, vl.z, f1.x, f1.y);
                    split2(vh.w, vl.w, f1.z, f1.w);
                }
                uint32_t s = swz(rowoff + c8 * 16u);
                *(uint4*)(ah + s) = vh;
                *(uint4*)(al + s) = vl;
            }
        }

        asm volatile("fence.proxy.async.shared::cta;" ::: "memory");
        __syncthreads();

        if (t == 0) {
            uint64_t dah = make_desc(sbase + OFF_A(buf));
            uint64_t dal = make_desc(sbase + OFF_A(buf) + 32768u);
            uint64_t ta[3] = {dah, dal, dah};
            uint64_t tb[3] = {dbh, dbh, dbl};
            uint32_t td = tmem + (uint32_t)buf * 128u;
            uint32_t en = 0;
#pragma unroll
            for (int term = 0; term < 3; term++) {
#pragma unroll
                for (int k = 0; k < 8; k++) {
                    uint64_t off = (uint64_t)((k >> 2) * 1024 + (k & 3) * 2);
                    asm volatile(
                        "{\n\t.reg .pred p;\n\t"
                        "setp.ne.u32 p, %4, 0;\n\t"
                        "tcgen05.mma.cta_group::1.kind::f16 [%0], %1, %2, %3, {%5, %5, %5, %5}, p;\n\t}"
                        :: "r"(td), "l"(ta[term] + off), "l"(tb[term] + off),
                           "r"(MMA_IDESC), "r"(en), "r"(0u) : "memory");
                    en = 1;
                }
            }
            asm volatile(
                "tcgen05.commit.cta_group::1.mbarrier::arrive::one.shared::cluster.b64 [%0];"
                :: "r"(s_ctrl + 8 + 8 * (uint32_t)buf) : "memory");
        }

        // Overlap: wait + epilogue the PREVIOUS tile while this MMA runs
        if (pend) { wait_pend(); epilogue(pend_m0, pend_nr, pend_buf, pend_e); }
        pend = true;
        pend_m0 = m0; pend_nr = nr; pend_buf = buf; pend_e = e;
        pend_par = (rel >> 1) & 1;
    }
    if (pend) { wait_pend(); epilogue(pend_m0, pend_nr, pend_buf, pend_e); }

    // Zero unmatched rows: one warp per row per iter (coalesced 512B),
    // 4x-unrolled independent index loads.
    {
        int n4 = (z1 - z0) * 32;
        const int* rl = &g_row_idx[4][z0];
        float4 zz = make_float4(0.f, 0.f, 0.f, 0.f);
        int i = t;
        for (; i + 3 * 256 < n4; i += 4 * 256) {
            int r0 = __ldg(rl + ((i) >> 5));
            int r1 = __ldg(rl + ((i + 256) >> 5));
            int r2 = __ldg(rl + ((i + 512) >> 5));
            int r3 = __ldg(rl + ((i + 768) >> 5));
            ((float4*)out)[(size_t)r0 * 32 + (i & 31)] = zz;
            ((float4*)out)[(size_t)r1 * 32 + ((i + 256) & 31)] = zz;
            ((float4*)out)[(size_t)r2 * 32 + ((i + 512) & 31)] = zz;
            ((float4*)out)[(size_t)r3 * 32 + ((i + 768) & 31)] = zz;
        }
        for (; i < n4; i += 256) {
            int r0 = __ldg(rl + (i >> 5));
            ((float4*)out)[(size_t)r0 * 32 + (i & 31)] = zz;
        }
    }

    __syncthreads();
    if (t == 0) {
        asm volatile("mbarrier.inval.shared.b64 [%0];" :: "r"(s_ctrl + 8) : "memory");
        asm volatile("mbarrier.inval.shared.b64 [%0];" :: "r"(s_ctrl + 16) : "memory");
    }
    __syncthreads();
    if (wid == 0) {
        asm volatile("tcgen05.dealloc.cta_group::1.sync.aligned.b32 %0, %1;"
                     :: "r"(tmem), "r"(256u));
    }
#endif
}

// ---------------- launch -----------------------------------------------------
extern "C" void kernel_launch(void* const* d_in, const int* in_sizes, int n_in,
                              void* d_out, int out_size) {
    const float* x = (const float*)d_in[0];
    const int* atom_numbers = (const int*)d_in[1];
    const float* W = (const float*)d_in[2];
    const float* bias = (const float*)d_in[3];
    const int* atom_cases = (const int*)d_in[4];
    float* out = (float*)d_out;

    int nrows = in_sizes[1];  // B * A

    k_reset<<<1, 32>>>();
    k_scatter<<<(nrows + 1023) / 1024, 1024>>>(atom_numbers, atom_cases, nrows);

    cudaFuncSetAttribute(k_wprep, cudaFuncAttributeMaxDynamicSharedMemorySize, 65536);
    k_wprep<<<NE, 256, 65536>>>(W);

    cudaFuncSetAttribute(k_gemm, cudaFuncAttributeMaxDynamicSharedMemorySize, SMEM_BYTES);
    k_gemm<<<NCTA, 256, SMEM_BYTES>>>(x, W, bias, out);
}

// round 6
// speedup vs baseline: 2.3989x; 1.1312x over previous
#include <cuda_runtime.h>
#include <cuda_bf16.h>
#include <cstdint>

#define CI 128
#define CO 128
#define NE 4
#define NB 5               // 4 experts + 1 "unmatched" bucket
#define MAXROWS (2048*128)
#define BM 128
#define NCTA 152           // persistent grid (GB300: 152 SMs)
#define NT 512             // threads per gemm CTA (16 warps)

// ---------------- scratch (__device__ globals; no dynamic alloc allowed) ----
__device__ int g_row_idx[NB][MAXROWS];
__device__ int g_count[NB];
// Pre-swizzled SMEM-image of W[e] (transposed to [N=CO rows, K=CI cols],
// K-major SW128 blocked layout), split into bf16 hi/lo.
__device__ __align__(16) unsigned char g_wimg_hi[NE][32768];
__device__ __align__(16) unsigned char g_wimg_lo[NE][32768];

// ---------------- small helpers ---------------------------------------------
__device__ __forceinline__ uint32_t smem_u32(const void* p) {
    uint32_t a;
    asm("{ .reg .u64 t; cvta.to.shared.u64 t, %1; cvt.u32.u64 %0, t; }"
        : "=r"(a) : "l"(p));
    return a;
}
__device__ __forceinline__ uint32_t swz(uint32_t off) {   // SW128: Swizzle<3,4,3>
    return off ^ ((off >> 3) & 0x70);
}

// pairwise fp32 -> bf16 hi/lo split: h packs {lo=cvt(a), hi=cvt(b)},
// l packs residuals likewise. (cvt.rn.bf16x2.f32 %0,hi_src,lo_src)
__device__ __forceinline__ void split2(uint32_t& h, uint32_t& l, float a, float b) {
    asm("cvt.rn.bf16x2.f32 %0, %1, %2;" : "=r"(h) : "f"(b), "f"(a));
    float ra = a - __uint_as_float(h << 16);
    float rb = b - __uint_as_float(h & 0xffff0000u);
    asm("cvt.rn.bf16x2.f32 %0, %1, %2;" : "=r"(l) : "f"(rb), "f"(ra));
}

// SMEM descriptor: SW128, version=1(Blackwell), SBO=64, LBO=1 (K-major)
static __device__ __forceinline__ uint64_t make_desc(uint32_t addr) {
    const uint64_t BASE = (uint64_t(2) << 61) | (uint64_t(1) << 46) |
                          (uint64_t(64) << 32) | (uint64_t(1) << 16);
    return BASE | ((uint64_t)(addr >> 4) & 0x3FFF);
}

// idesc kind::f16: F32 accum(1<<4), a=BF16(1<<7), b=BF16(1<<10),
// N=128((128/8)<<17), M=128((128/16)<<24)
#define MMA_IDESC 0x8200490u

// Blocked-atom byte offset for element (row, col) in a [128 x 128] bf16 K-major
// SW128 tile: atoms of 8 rows x 64 cols (1024B), atom_offset = atom_row + atom_col*16.
__device__ __forceinline__ uint32_t tile_off_128r(uint32_t row, uint32_t col) {
    return ((row >> 3) + (col >> 6) * 16u) * 1024u + (row & 7u) * 128u + (col & 63u) * 2u;
}

// ---------------- prep: reset ------------------------------------------------
__global__ void k_reset() {
    if (threadIdx.x < NB) g_count[threadIdx.x] = 0;
}

// ---------------- fused prep: scatter blocks + wprep blocks -------------------
// Blocks [0, NS): block-aggregated bucketing (1 atomic/bucket/block).
// Blocks [NS, NS+NE): build per-expert swizzled bf16 hi/lo W images.
__global__ void __launch_bounds__(1024)
k_prep(const int* __restrict__ atom_numbers, const int* __restrict__ atom_cases,
       const float* __restrict__ W, int nrows, int nscatter) {
    if ((int)blockIdx.x >= nscatter) {
        // ---- wprep: coalesced (o fastest) reads from global W
        int e = blockIdx.x - nscatter;
        const float* We = W + (size_t)e * CI * CO;
        for (int item = threadIdx.x; item < CO * 16; item += 1024) {
            int o = item & 127;        // output channel (B row), lane-consecutive
            int kc = item >> 7;        // 8-wide K chunk
            uint32_t ph[4], pl[4];
#pragma unroll
            for (int j = 0; j < 4; j++) {
                float a = __ldg(We + (kc * 8 + 2 * j) * CO + o);
                float b = __ldg(We + (kc * 8 + 2 * j + 1) * CO + o);
                split2(ph[j], pl[j], a, b);
            }
            uint32_t s = swz(tile_off_128r(o, kc * 8));
            *(uint4*)((unsigned char*)g_wimg_hi[e] + s) =
                make_uint4(ph[0], ph[1], ph[2], ph[3]);
            *(uint4*)((unsigned char*)g_wimg_lo[e] + s) =
                make_uint4(pl[0], pl[1], pl[2], pl[3]);
        }
        return;
    }

    // ---- scatter
    __shared__ int wcnt[NB][32];
    __shared__ int sbase[NB];
    int t = threadIdx.x, w = t >> 5, lane = t & 31;
    int row = blockIdx.x * 1024 + t;
    bool valid = row < nrows;
    int an = valid ? atom_numbers[row] : -1234567;
    int c0 = __ldg(atom_cases + 0), c1 = __ldg(atom_cases + 1);
    int c2 = __ldg(atom_cases + 2), c3 = __ldg(atom_cases + 3);
    int e = 4;                       // bucket 4 = unmatched (needs zero output)
    if (an == c0) e = 0;
    else if (an == c1) e = 1;
    else if (an == c2) e = 2;
    else if (an == c3) e = 3;
    if (!valid) e = -1;

    int myrank = 0;
#pragma unroll
    for (int b = 0; b < NB; b++) {
        unsigned m = __ballot_sync(0xffffffffu, e == b);
        if (e == b) myrank = __popc(m & ((1u << lane) - 1u));
        if (lane == 0) wcnt[b][w] = __popc(m);
    }
    __syncthreads();
    if (t < NB) {
        int s = 0;
#pragma unroll
        for (int i = 0; i < 32; i++) { int v = wcnt[t][i]; wcnt[t][i] = s; s += v; }
        sbase[t] = s ? atomicAdd(&g_count[t], s) : 0;
    }
    __syncthreads();
    if (e >= 0) g_row_idx[e][sbase[e] + wcnt[e][w] + myrank] = row;
}

// ---------------- persistent pipelined grouped GEMM ---------------------------
// Double-buffered A in smem, double-buffered D in TMEM, two mbarriers.
// Per-iteration: gather A(t) -> sync -> issue MMA(t) -> wait(t-1)/epilogue(t-1).
// tcgen05: D = A_hi*B_hi + A_lo*B_hi + A_hi*B_lo (bf16 split, fp32 TMEM accum).
#define OFF_A(buf)  ((buf) * 65536u)            // A_hi at +0, A_lo at +32768
#define OFF_B_HI 131072u
#define OFF_B_LO 163840u
#define OFF_CTRL 196608u
#define SMEM_BYTES (196608 + 1024 + 1024)

__global__ void __launch_bounds__(NT, 1)
k_gemm(const float* __restrict__ x, const float* __restrict__ W,
       const float* __restrict__ bias, float* __restrict__ out) {
    int t = threadIdx.x;

    // Tile partition (uniform across threads)
    int c[NE], pfx[NE + 1];
    pfx[0] = 0;
#pragma unroll
    for (int e = 0; e < NE; e++) {
        c[e] = g_count[e];
        pfx[e + 1] = pfx[e] + ((c[e] + BM - 1) >> 7);
    }
    int total = pfx[NE];
    int begin = (int)((long long)total * blockIdx.x / gridDim.x);
    int end   = (int)((long long)total * (blockIdx.x + 1) / gridDim.x);

    // Bucket-4 (unmatched) zero slice for this CTA
    int cnt4 = g_count[4];
    int z0 = (int)((long long)cnt4 * blockIdx.x / gridDim.x);
    int z1 = (int)((long long)cnt4 * (blockIdx.x + 1) / gridDim.x);

#if defined(__CUDA_ARCH__) && !defined(__CUDA_ARCH_FEAT_SM103_ALL)
    // ---------------- fallback: fp32 SIMT (JIT-safety only) ------------------
    for (int tile = begin; tile < end; tile++) {
        int e = 0;
        while (tile >= pfx[e + 1]) e++;
        int m0 = (tile - pfx[e]) * BM;
        int nr = min(BM, c[e] - m0);
        for (int idx = t; idx < nr * CO; idx += NT) {
            int m = idx >> 7, o = idx & 127;
            int grow = g_row_idx[e][m0 + m];
            const float* xr = x + (size_t)grow * CI;
            const float* wc = W + (size_t)e * CI * CO + o;
            float acc = bias[e * CO + o];
            for (int k = 0; k < CI; k++) acc += xr[k] * wc[(size_t)k * CO];
            out[(size_t)grow * CO + o] = fmaxf(acc, 0.f);
        }
    }
    for (int i = z0 * 32 + t; i < z1 * 32; i += NT) {
        int grow = g_row_idx[4][i >> 5];
        ((float4*)out)[(size_t)grow * 32 + (i & 31)] = make_float4(0.f, 0.f, 0.f, 0.f);
    }
#else
    // ---------------- tcgen05 path -------------------------------------------
    extern __shared__ unsigned char smraw[];
    uint32_t sraw = smem_u32(smraw);
    uint32_t sbase = (sraw + 1023u) & ~1023u;          // 1024-align for SW128
    unsigned char* sm = smraw + (sbase - sraw);
    uint32_t s_ctrl = sbase + OFF_CTRL;   // [0]=tmem, [8],[16]=mbars, [64..]=bias

    int wid = t >> 5, lane = t & 31;

    if (wid == 0) {
        asm volatile("tcgen05.alloc.cta_group::1.sync.aligned.shared::cta.b32 [%0], %1;"
                     :: "r"(s_ctrl), "r"(256u) : "memory");
        asm volatile("tcgen05.relinquish_alloc_permit.cta_group::1.sync.aligned;");
    }
    if (t == 0) {
        asm volatile("mbarrier.init.shared.b64 [%0], %1;"
                     :: "r"(s_ctrl + 8), "r"(1u) : "memory");
        asm volatile("mbarrier.init.shared.b64 [%0], %1;"
                     :: "r"(s_ctrl + 16), "r"(1u) : "memory");
    }
    __syncthreads();
    uint32_t tmem;
    asm volatile("ld.shared.b32 %0, [%1];" : "=r"(tmem) : "r"(s_ctrl));

    uint64_t dbh = make_desc(sbase + OFF_B_HI);
    uint64_t dbl = make_desc(sbase + OFF_B_LO);

    // pending-tile state
    bool pend = false;
    int pend_m0 = 0, pend_nr = 0, pend_buf = 0, pend_par = 0, pend_e = 0;

    // epilogue: 16 warps, each ONE LDTM.x32 — warp wid reads subpartition
    // (wid&3) (rows) x column block (wid>>2)*32; +bias, relu, scatter-store.
    auto epilogue = [&](int em0, int enr, int ebuf, int ee) {
        int m = (wid & 3) * 32 + lane;
        int cb = wid >> 2;                       // column block 0..3
        bool val = m < enr;
        int grow = val ? __ldg(&g_row_idx[ee][em0 + m]) : 0;
        float* op = out + (size_t)grow * CO + cb * 32;
        const float* bsm = (const float*)(sm + OFF_CTRL + 64) + cb * 32;
        uint32_t td = tmem + (uint32_t)ebuf * 128u + (uint32_t)cb * 32u;
        uint32_t d[32];
        asm volatile(
            "tcgen05.ld.sync.aligned.32x32b.x32.b32 "
            "{%0, %1, %2, %3, %4, %5, %6, %7, "
            " %8, %9, %10, %11, %12, %13, %14, %15, "
            " %16, %17, %18, %19, %20, %21, %22, %23, "
            " %24, %25, %26, %27, %28, %29, %30, %31}, [%32];"
            : "=r"(d[0]),  "=r"(d[1]),  "=r"(d[2]),  "=r"(d[3]),
              "=r"(d[4]),  "=r"(d[5]),  "=r"(d[6]),  "=r"(d[7]),
              "=r"(d[8]),  "=r"(d[9]),  "=r"(d[10]), "=r"(d[11]),
              "=r"(d[12]), "=r"(d[13]), "=r"(d[14]), "=r"(d[15]),
              "=r"(d[16]), "=r"(d[17]), "=r"(d[18]), "=r"(d[19]),
              "=r"(d[20]), "=r"(d[21]), "=r"(d[22]), "=r"(d[23]),
              "=r"(d[24]), "=r"(d[25]), "=r"(d[26]), "=r"(d[27]),
              "=r"(d[28]), "=r"(d[29]), "=r"(d[30]), "=r"(d[31])
            : "r"(td));
        asm volatile("tcgen05.wait::ld.sync.aligned;" ::: "memory");
#pragma unroll
        for (int j = 0; j < 32; j += 4) {
            float4 v;
            v.x = fmaxf(__uint_as_float(d[j + 0]) + bsm[j + 0], 0.f);
            v.y = fmaxf(__uint_as_float(d[j + 1]) + bsm[j + 1], 0.f);
            v.z = fmaxf(__uint_as_float(d[j + 2]) + bsm[j + 2], 0.f);
            v.w = fmaxf(__uint_as_float(d[j + 3]) + bsm[j + 3], 0.f);
            if (val) *(float4*)(op + j) = v;
        }
    };
    auto wait_pend = [&]() {
        uint32_t mb = s_ctrl + 8 + 8 * (uint32_t)pend_buf;
        uint32_t done = 0;
        while (!done) {
            asm volatile(
                "{\n\t.reg .pred p;\n\t"
                "mbarrier.try_wait.parity.acquire.cta.shared::cta.b64 p, [%1], %2, 0x989680;\n\t"
                "selp.b32 %0, 1, 0, p;\n\t}"
                : "=r"(done) : "r"(mb), "r"((uint32_t)pend_par) : "memory");
        }
        asm volatile("tcgen05.fence::after_thread_sync;" ::: "memory");
    };

    int cur_e = -1;
    for (int tile = begin; tile < end; tile++) {
        int e = 0;
        while (tile >= pfx[e + 1]) e++;
        int m0 = (tile - pfx[e]) * BM;
        int nr = min(BM, c[e] - m0);
        int rel = tile - begin;
        int buf = rel & 1;

        // Expert change: drain pending MMA (it reads B), then reload B + bias
        if (e != cur_e) {
            if (pend) { wait_pend(); epilogue(pend_m0, pend_nr, pend_buf, pend_e); pend = false; }
            const uint4* gh = (const uint4*)g_wimg_hi[e];
            const uint4* gl = (const uint4*)g_wimg_lo[e];
            uint4* bh = (uint4*)(sm + OFF_B_HI);
            uint4* bl = (uint4*)(sm + OFF_B_LO);
#pragma unroll
            for (int i = 0; i < 4; i++) {
                bh[t + i * NT] = gh[t + i * NT];
                bl[t + i * NT] = gl[t + i * NT];
            }
            if (t < CO) ((float*)(sm + OFF_CTRL + 64))[t] = bias[e * CO + t];
            cur_e = e;
        }

        // Gather + split-convert x rows into A[buf]: 4 threads per row,
        // each handles a 32-col quarter; all 8 loads batched before converts.
        {
            int r = t >> 2, q = t & 3;
            bool val = r < nr;
            float4 f[8];
            if (val) {
                int grow = __ldg(&g_row_idx[e][m0 + r]);
                const float4* xr = (const float4*)(x + (size_t)grow * CI + q * 32);
#pragma unroll
                for (int i = 0; i < 8; i++) f[i] = xr[i];
            } else {
#pragma unroll
                for (int i = 0; i < 8; i++) f[i] = make_float4(0.f, 0.f, 0.f, 0.f);
            }
            uint32_t base = ((uint32_t)(r >> 3) + (uint32_t)(q >> 1) * 16u) * 1024u +
                            (r & 7u) * 128u + (uint32_t)(q & 1) * 64u;
            unsigned char* ah = sm + OFF_A(buf);
            unsigned char* al = ah + 32768;
#pragma unroll
            for (int c8 = 0; c8 < 4; c8++) {
                uint4 vh, vl;
                float4 f0 = f[c8 * 2], f1 = f[c8 * 2 + 1];
                split2(vh.x, vl.x, f0.x, f0.y);
                split2(vh.y, vl.y, f0.z, f0.w);
                split2(vh.z, vl.z, f1.x, f1.y);
                split2(vh.w, vl.w, f1.z, f1.w);
                uint32_t s = swz(base + c8 * 16u);
                *(uint4*)(ah + s) = vh;
                *(uint4*)(al + s) = vl;
            }
        }

        asm volatile("fence.proxy.async.shared::cta;" ::: "memory");
        __syncthreads();

        if (t == 0) {
            uint64_t dah = make_desc(sbase + OFF_A(buf));
            uint64_t dal = make_desc(sbase + OFF_A(buf) + 32768u);
            uint64_t ta[3] = {dah, dal, dah};
            uint64_t tb[3] = {dbh, dbh, dbl};
            uint32_t td = tmem + (uint32_t)buf * 128u;
            uint32_t en = 0;
#pragma unroll
            for (int term = 0; term < 3; term++) {
#pragma unroll
                for (int k = 0; k < 8; k++) {
                    uint64_t off = (uint64_t)((k >> 2) * 1024 + (k & 3) * 2);
                    asm volatile(
                        "{\n\t.reg .pred p;\n\t"
                        "setp.ne.u32 p, %4, 0;\n\t"
                        "tcgen05.mma.cta_group::1.kind::f16 [%0], %1, %2, %3, {%5, %5, %5, %5}, p;\n\t}"
                        :: "r"(td), "l"(ta[term] + off), "l"(tb[term] + off),
                           "r"(MMA_IDESC), "r"(en), "r"(0u) : "memory");
                    en = 1;
                }
            }
            asm volatile(
                "tcgen05.commit.cta_group::1.mbarrier::arrive::one.shared::cluster.b64 [%0];"
                :: "r"(s_ctrl + 8 + 8 * (uint32_t)buf) : "memory");
        }

        // Overlap: wait + epilogue the PREVIOUS tile while this MMA runs
        if (pend) { wait_pend(); epilogue(pend_m0, pend_nr, pend_buf, pend_e); }
        pend = true;
        pend_m0 = m0; pend_nr = nr; pend_buf = buf; pend_e = e;
        pend_par = (rel >> 1) & 1;
    }
    if (pend) { wait_pend(); epilogue(pend_m0, pend_nr, pend_buf, pend_e); }

    // Zero unmatched rows: coalesced 512B per warp-iter, 4x-unrolled indices.
    {
        int n4 = (z1 - z0) * 32;
        const int* rl = &g_row_idx[4][z0];
        float4 zz = make_float4(0.f, 0.f, 0.f, 0.f);
        int i = t;
        for (; i + 3 * NT < n4; i += 4 * NT) {
            int r0 = __ldg(rl + ((i) >> 5));
            int r1 = __ldg(rl + ((i + NT) >> 5));
            int r2 = __ldg(rl + ((i + 2 * NT) >> 5));
            int r3 = __ldg(rl + ((i + 3 * NT) >> 5));
            ((float4*)out)[(size_t)r0 * 32 + (i & 31)] = zz;
            ((float4*)out)[(size_t)r1 * 32 + ((i + NT) & 31)] = zz;
            ((float4*)out)[(size_t)r2 * 32 + ((i + 2 * NT) & 31)] = zz;
            ((float4*)out)[(size_t)r3 * 32 + ((i + 3 * NT) & 31)] = zz;
        }
        for (; i < n4; i += NT) {
            int r0 = __ldg(rl + (i >> 5));
            ((float4*)out)[(size_t)r0 * 32 + (i & 31)] = zz;
        }
    }

    __syncthreads();
    if (t == 0) {
        asm volatile("mbarrier.inval.shared.b64 [%0];" :: "r"(s_ctrl + 8) : "memory");
        asm volatile("mbarrier.inval.shared.b64 [%0];" :: "r"(s_ctrl + 16) : "memory");
    }
    __syncthreads();
    if (wid == 0) {
        asm volatile("tcgen05.dealloc.cta_group::1.sync.aligned.b32 %0, %1;"
                     :: "r"(tmem), "r"(256u));
    }
#endif
}

// ---------------- launch -----------------------------------------------------
extern "C" void kernel_launch(void* const* d_in, const int* in_sizes, int n_in,
                              void* d_out, int out_size) {
    const float* x = (const float*)d_in[0];
    const int* atom_numbers = (const int*)d_in[1];
    const float* W = (const float*)d_in[2];
    const float* bias = (const float*)d_in[3];
    const int* atom_cases = (const int*)d_in[4];
    float* out = (float*)d_out;

    int nrows = in_sizes[1];  // B * A
    int nscatter = (nrows + 1023) / 1024;

    k_reset<<<1, 32>>>();
    k_prep<<<nscatter + NE, 1024>>>(atom_numbers, atom_cases, W, nrows, nscatter);

    cudaFuncSetAttribute(k_gemm, cudaFuncAttributeMaxDynamicSharedMemorySize, SMEM_BYTES);
    k_gemm<<<NCTA, NT, SMEM_BYTES>>>(x, W, bias, out);
}

// round 7
// speedup vs baseline: 2.5164x; 1.0490x over previous
#include <cuda_runtime.h>
#include <cuda_bf16.h>
#include <cstdint>

#define CI 128
#define CO 128
#define NE 4
#define NB 5               // 4 experts + 1 "unmatched" bucket
#define MAXROWS (2048*128)
#define BM 128
#define NCTA 152           // persistent grid (GB300: 152 SMs)
#define NT 512             // threads per gemm CTA (16 warps)

// ---------------- scratch (__device__ globals; no dynamic alloc allowed) ----
__device__ int g_row_idx[NB][MAXROWS];
__device__ int g_count[NB];   // zero-initialized at load; re-zeroed by k_gemm tail
// Pre-swizzled SMEM-image of W[e] (transposed to [N=CO rows, K=CI cols],
// K-major SW128 blocked layout), split into bf16 hi/lo.
__device__ __align__(16) unsigned char g_wimg_hi[NE][32768];
__device__ __align__(16) unsigned char g_wimg_lo[NE][32768];

// ---------------- small helpers ---------------------------------------------
__device__ __forceinline__ uint32_t smem_u32(const void* p) {
    uint32_t a;
    asm("{ .reg .u64 t; cvta.to.shared.u64 t, %1; cvt.u32.u64 %0, t; }"
        : "=r"(a) : "l"(p));
    return a;
}
__device__ __forceinline__ uint32_t swz(uint32_t off) {   // SW128: Swizzle<3,4,3>
    return off ^ ((off >> 3) & 0x70);
}

// pairwise fp32 -> bf16 hi/lo split: h packs {lo=cvt(a), hi=cvt(b)},
// l packs residuals likewise. (cvt.rn.bf16x2.f32 %0,hi_src,lo_src)
__device__ __forceinline__ void split2(uint32_t& h, uint32_t& l, float a, float b) {
    asm("cvt.rn.bf16x2.f32 %0, %1, %2;" : "=r"(h) : "f"(b), "f"(a));
    float ra = a - __uint_as_float(h << 16);
    float rb = b - __uint_as_float(h & 0xffff0000u);
    asm("cvt.rn.bf16x2.f32 %0, %1, %2;" : "=r"(l) : "f"(rb), "f"(ra));
}

// SMEM descriptor: SW128, version=1(Blackwell), SBO=64, LBO=1 (K-major)
static __device__ __forceinline__ uint64_t make_desc(uint32_t addr) {
    const uint64_t BASE = (uint64_t(2) << 61) | (uint64_t(1) << 46) |
                          (uint64_t(64) << 32) | (uint64_t(1) << 16);
    return BASE | ((uint64_t)(addr >> 4) & 0x3FFF);
}

// idesc kind::f16: F32 accum(1<<4), a=BF16(1<<7), b=BF16(1<<10),
// N=128((128/8)<<17), M=128((128/16)<<24)
#define MMA_IDESC 0x8200490u

// Blocked-atom byte offset for element (row, col) in a [128 x 128] bf16 K-major
// SW128 tile: atoms of 8 rows x 64 cols (1024B), atom_offset = atom_row + atom_col*16.
__device__ __forceinline__ uint32_t tile_off_128r(uint32_t row, uint32_t col) {
    return ((row >> 3) + (col >> 6) * 16u) * 1024u + (row & 7u) * 128u + (col & 63u) * 2u;
}

// ---------------- fused prep: scatter(+zero) blocks + wprep blocks ------------
// Blocks [0, NS): block-aggregated bucketing + cooperative zeroing of
//                 unmatched output rows (moved here from the gemm tail).
// Blocks [NS, NS+NE): build per-expert swizzled bf16 hi/lo W images.
__global__ void __launch_bounds__(1024)
k_prep(const int* __restrict__ atom_numbers, const int* __restrict__ atom_cases,
       const float* __restrict__ W, float* __restrict__ out,
       int nrows, int nscatter) {
    if ((int)blockIdx.x >= nscatter) {
        // ---- wprep: coalesced (o fastest) reads from global W
        int e = blockIdx.x - nscatter;
        const float* We = W + (size_t)e * CI * CO;
        for (int item = threadIdx.x; item < CO * 16; item += 1024) {
            int o = item & 127;        // output channel (B row), lane-consecutive
            int kc = item >> 7;        // 8-wide K chunk
            uint32_t ph[4], pl[4];
#pragma unroll
            for (int j = 0; j < 4; j++) {
                float a = __ldg(We + (kc * 8 + 2 * j) * CO + o);
                float b = __ldg(We + (kc * 8 + 2 * j + 1) * CO + o);
                split2(ph[j], pl[j], a, b);
            }
            uint32_t s = swz(tile_off_128r(o, kc * 8));
            *(uint4*)((unsigned char*)g_wimg_hi[e] + s) =
                make_uint4(ph[0], ph[1], ph[2], ph[3]);
            *(uint4*)((unsigned char*)g_wimg_lo[e] + s) =
                make_uint4(pl[0], pl[1], pl[2], pl[3]);
        }
        return;
    }

    // ---- scatter + zero
    __shared__ int wcnt[NB][32];
    __shared__ int sbase[NB];
    int t = threadIdx.x, w = t >> 5, lane = t & 31;
    int row = blockIdx.x * 1024 + t;
    bool valid = row < nrows;
    int an = valid ? atom_numbers[row] : -1234567;
    int c0 = __ldg(atom_cases + 0), c1 = __ldg(atom_cases + 1);
    int c2 = __ldg(atom_cases + 2), c3 = __ldg(atom_cases + 3);
    int e = 4;                       // bucket 4 = unmatched (zero output)
    if (an == c0) e = 0;
    else if (an == c1) e = 1;
    else if (an == c2) e = 2;
    else if (an == c3) e = 3;
    if (!valid) e = -1;

    // Zero unmatched rows cooperatively: 32 lanes x float4 = one 512B row.
    {
        unsigned mu = __ballot_sync(0xffffffffu, e == 4);
        float4 zz = make_float4(0.f, 0.f, 0.f, 0.f);
        while (mu) {
            int b = __ffs(mu) - 1;
            mu &= mu - 1;
            int zr = __shfl_sync(0xffffffffu, row, b);
            ((float4*)out)[(size_t)zr * 32 + lane] = zz;
        }
    }

    int myrank = 0;
#pragma unroll
    for (int b = 0; b < NB; b++) {
        unsigned m = __ballot_sync(0xffffffffu, e == b);
        if (e == b) myrank = __popc(m & ((1u << lane) - 1u));
        if (lane == 0) wcnt[b][w] = __popc(m);
    }
    __syncthreads();
    if (t < NB) {
        int s = 0;
#pragma unroll
        for (int i = 0; i < 32; i++) { int v = wcnt[t][i]; wcnt[t][i] = s; s += v; }
        sbase[t] = s ? atomicAdd(&g_count[t], s) : 0;
    }
    __syncthreads();
    if (e >= 0) g_row_idx[e][sbase[e] + wcnt[e][w] + myrank] = row;
}

// ---------------- persistent pipelined grouped GEMM ---------------------------
// Double-buffered A in smem, double-buffered D in TMEM, two mbarriers,
// 4-slot row-index prefetch ring (indices for tile t+1 loaded during tile t).
// tcgen05: D = A_hi*B_hi + A_lo*B_hi + A_hi*B_lo (bf16 split, fp32 TMEM accum).
#define OFF_A(buf)  ((buf) * 65536u)            // A_hi at +0, A_lo at +32768
#define OFF_B_HI 131072u
#define OFF_B_LO 163840u
#define OFF_CTRL 196608u
#define OFF_IDX  197632u                        // 4 slots x 128 ints = 2KB
#define SMEM_BYTES (196608 + 1024 + 2048 + 1024)

__global__ void __launch_bounds__(NT, 1)
k_gemm(const float* __restrict__ x, const float* __restrict__ W,
       const float* __restrict__ bias, float* __restrict__ out) {
    int t = threadIdx.x;

    // Tile partition (uniform across threads)
    int c[NE], pfx[NE + 1];
    pfx[0] = 0;
#pragma unroll
    for (int e = 0; e < NE; e++) {
        c[e] = g_count[e];
        pfx[e + 1] = pfx[e] + ((c[e] + BM - 1) >> 7);
    }
    int total = pfx[NE];
    int begin = (int)((long long)total * blockIdx.x / gridDim.x);
    int end   = (int)((long long)total * (blockIdx.x + 1) / gridDim.x);

#if defined(__CUDA_ARCH__) && !defined(__CUDA_ARCH_FEAT_SM103_ALL)
    // ---------------- fallback: fp32 SIMT (JIT-safety only) ------------------
    for (int tile = begin; tile < end; tile++) {
        int e = 0;
        while (tile >= pfx[e + 1]) e++;
        int m0 = (tile - pfx[e]) * BM;
        int nr = min(BM, c[e] - m0);
        for (int idx = t; idx < nr * CO; idx += NT) {
            int m = idx >> 7, o = idx & 127;
            int grow = g_row_idx[e][m0 + m];
            const float* xr = x + (size_t)grow * CI;
            const float* wc = W + (size_t)e * CI * CO + o;
            float acc = bias[e * CO + o];
            for (int k = 0; k < CI; k++) acc += xr[k] * wc[(size_t)k * CO];
            out[(size_t)grow * CO + o] = fmaxf(acc, 0.f);
        }
    }
    __syncthreads();
    if (blockIdx.x == 0 && t < NB) g_count[t] = 0;
#else
    // ---------------- tcgen05 path -------------------------------------------
    extern __shared__ unsigned char smraw[];
    uint32_t sraw = smem_u32(smraw);
    uint32_t sbase = (sraw + 1023u) & ~1023u;          // 1024-align for SW128
    unsigned char* sm = smraw + (sbase - sraw);
    uint32_t s_ctrl = sbase + OFF_CTRL;   // [0]=tmem, [8],[16]=mbars, [64..]=bias
    int* s_idx = (int*)(sm + OFF_IDX);    // [4][BM] row-index ring

    int wid = t >> 5, lane = t & 31;

    if (wid == 0) {
        asm volatile("tcgen05.alloc.cta_group::1.sync.aligned.shared::cta.b32 [%0], %1;"
                     :: "r"(s_ctrl), "r"(256u) : "memory");
        asm volatile("tcgen05.relinquish_alloc_permit.cta_group::1.sync.aligned;");
    }
    if (t == 0) {
        asm volatile("mbarrier.init.shared.b64 [%0], %1;"
                     :: "r"(s_ctrl + 8), "r"(1u) : "memory");
        asm volatile("mbarrier.init.shared.b64 [%0], %1;"
                     :: "r"(s_ctrl + 16), "r"(1u) : "memory");
    }

    // Prefetch indices for tile `nt` into ring slot nt&3 (threads 0..127).
    auto prefetch_idx = [&](int nt) {
        if (nt >= end || t >= BM) return;
        int e2 = 0;
        while (nt >= pfx[e2 + 1]) e2++;
        int m02 = (nt - pfx[e2]) * BM;
        int nr2 = min(BM, c[e2] - m02);
        int v = (t < nr2) ? __ldg(&g_row_idx[e2][m02 + t]) : 0;
        s_idx[(nt & 3) * BM + t] = v;
    };
    prefetch_idx(begin);
    __syncthreads();
    uint32_t tmem;
    asm volatile("ld.shared.b32 %0, [%1];" : "=r"(tmem) : "r"(s_ctrl));

    uint64_t dbh = make_desc(sbase + OFF_B_HI);
    uint64_t dbl = make_desc(sbase + OFF_B_LO);

    // pending-tile state
    bool pend = false;
    int pend_nr = 0, pend_buf = 0, pend_par = 0, pend_slot = 0;

    // epilogue: 16 warps, each ONE LDTM.x32 — warp wid reads row subpartition
    // (wid&3) x column block (wid>>2)*32; +bias, relu, scatter-store.
    auto epilogue = [&](int enr, int ebuf, int eslot) {
        int m = (wid & 3) * 32 + lane;
        int cb = wid >> 2;
        bool val = m < enr;
        int grow = s_idx[eslot * BM + (val ? m : 0)];
        float* op = out + (size_t)grow * CO + cb * 32;
        const float* bsm = (const float*)(sm + OFF_CTRL + 64) + cb * 32;
        uint32_t td = tmem + (uint32_t)ebuf * 128u + (uint32_t)cb * 32u;
        uint32_t d[32];
        asm volatile(
            "tcgen05.ld.sync.aligned.32x32b.x32.b32 "
            "{%0, %1, %2, %3, %4, %5, %6, %7, "
            " %8, %9, %10, %11, %12, %13, %14, %15, "
            " %16, %17, %18, %19, %20, %21, %22, %23, "
            " %24, %25, %26, %27, %28, %29, %30, %31}, [%32];"
            : "=r"(d[0]),  "=r"(d[1]),  "=r"(d[2]),  "=r"(d[3]),
              "=r"(d[4]),  "=r"(d[5]),  "=r"(d[6]),  "=r"(d[7]),
              "=r"(d[8]),  "=r"(d[9]),  "=r"(d[10]), "=r"(d[11]),
              "=r"(d[12]), "=r"(d[13]), "=r"(d[14]), "=r"(d[15]),
              "=r"(d[16]), "=r"(d[17]), "=r"(d[18]), "=r"(d[19]),
              "=r"(d[20]), "=r"(d[21]), "=r"(d[22]), "=r"(d[23]),
              "=r"(d[24]), "=r"(d[25]), "=r"(d[26]), "=r"(d[27]),
              "=r"(d[28]), "=r"(d[29]), "=r"(d[30]), "=r"(d[31])
            : "r"(td));
        asm volatile("tcgen05.wait::ld.sync.aligned;" ::: "memory");
#pragma unroll
        for (int j = 0; j < 32; j += 4) {
            float4 v;
            v.x = fmaxf(__uint_as_float(d[j + 0]) + bsm[j + 0], 0.f);
            v.y = fmaxf(__uint_as_float(d[j + 1]) + bsm[j + 1], 0.f);
            v.z = fmaxf(__uint_as_float(d[j + 2]) + bsm[j + 2], 0.f);
            v.w = fmaxf(__uint_as_float(d[j + 3]) + bsm[j + 3], 0.f);
            if (val) *(float4*)(op + j) = v;
        }
    };
    auto wait_pend = [&]() {
        uint32_t mb = s_ctrl + 8 + 8 * (uint32_t)pend_buf;
        uint32_t done = 0;
        while (!done) {
            asm volatile(
                "{\n\t.reg .pred p;\n\t"
                "mbarrier.try_wait.parity.acquire.cta.shared::cta.b64 p, [%1], %2, 0x989680;\n\t"
                "selp.b32 %0, 1, 0, p;\n\t}"
                : "=r"(done) : "r"(mb), "r"((uint32_t)pend_par) : "memory");
        }
        asm volatile("tcgen05.fence::after_thread_sync;" ::: "memory");
    };

    int cur_e = -1;
    for (int tile = begin; tile < end; tile++) {
        int e = 0;
        while (tile >= pfx[e + 1]) e++;
        int m0 = (tile - pfx[e]) * BM;
        int nr = min(BM, c[e] - m0);
        int rel = tile - begin;
        int buf = rel & 1;
        int slot = tile & 3;

        // Expert change: drain pending MMA (it reads B), then reload B + bias
        if (e != cur_e) {
            if (pend) { wait_pend(); epilogue(pend_nr, pend_buf, pend_slot); pend = false; }
            const uint4* gh = (const uint4*)g_wimg_hi[e];
            const uint4* gl = (const uint4*)g_wimg_lo[e];
            uint4* bh = (uint4*)(sm + OFF_B_HI);
            uint4* bl = (uint4*)(sm + OFF_B_LO);
#pragma unroll
            for (int i = 0; i < 4; i++) {
                bh[t + i * NT] = gh[t + i * NT];
                bl[t + i * NT] = gl[t + i * NT];
            }
            if (t < CO) ((float*)(sm + OFF_CTRL + 64))[t] = bias[e * CO + t];
            cur_e = e;
        }

        // Gather + split-convert x rows into A[buf]: 4 threads per row,
        // indices from smem ring (prefetched last tile) — single DRAM hop.
        {
            int r = t >> 2, q = t & 3;
            bool val = r < nr;
            int grow = s_idx[slot * BM + r];
            float4 f[8];
            if (val) {
                const float4* xr = (const float4*)(x + (size_t)grow * CI + q * 32);
#pragma unroll
                for (int i = 0; i < 8; i++) f[i] = xr[i];
            } else {
#pragma unroll
                for (int i = 0; i < 8; i++) f[i] = make_float4(0.f, 0.f, 0.f, 0.f);
            }
            uint32_t base = ((uint32_t)(r >> 3) + (uint32_t)(q >> 1) * 16u) * 1024u +
                            (r & 7u) * 128u + (uint32_t)(q & 1) * 64u;
            unsigned char* ah = sm + OFF_A(buf);
            unsigned char* al = ah + 32768;
#pragma unroll
            for (int c8 = 0; c8 < 4; c8++) {
                uint4 vh, vl;
                float4 f0 = f[c8 * 2], f1 = f[c8 * 2 + 1];
                split2(vh.x, vl.x, f0.x, f0.y);
                split2(vh.y, vl.y, f0.z, f0.w);
                split2(vh.z, vl.z, f1.x, f1.y);
                split2(vh.w, vl.w, f1.z, f1.w);
                uint32_t s = swz(base + c8 * 16u);
                *(uint4*)(ah + s) = vh;
                *(uint4*)(al + s) = vl;
            }
        }

        // Prefetch next tile's indices (slot (tile+1)&3; consumed after sync
        // next iteration; old content = tile-3, whose epilogue is done).
        prefetch_idx(tile + 1);

        asm volatile("fence.proxy.async.shared::cta;" ::: "memory");
        __syncthreads();

        if (t == 0) {
            uint64_t dah = make_desc(sbase + OFF_A(buf));
            uint64_t dal = make_desc(sbase + OFF_A(buf) + 32768u);
            uint64_t ta[3] = {dah, dal, dah};
            uint64_t tb[3] = {dbh, dbh, dbl};
            uint32_t td = tmem + (uint32_t)buf * 128u;
            uint32_t en = 0;
#pragma unroll
            for (int term = 0; term < 3; term++) {
#pragma unroll
                for (int k = 0; k < 8; k++) {
                    uint64_t off = (uint64_t)((k >> 2) * 1024 + (k & 3) * 2);
                    asm volatile(
                        "{\n\t.reg .pred p;\n\t"
                        "setp.ne.u32 p, %4, 0;\n\t"
                        "tcgen05.mma.cta_group::1.kind::f16 [%0], %1, %2, %3, {%5, %5, %5, %5}, p;\n\t}"
                        :: "r"(td), "l"(ta[term] + off), "l"(tb[term] + off),
                           "r"(MMA_IDESC), "r"(en), "r"(0u) : "memory");
                    en = 1;
                }
            }
            asm volatile(
                "tcgen05.commit.cta_group::1.mbarrier::arrive::one.shared::cluster.b64 [%0];"
                :: "r"(s_ctrl + 8 + 8 * (uint32_t)buf) : "memory");
        }

        // Overlap: wait + epilogue the PREVIOUS tile while this MMA runs
        if (pend) { wait_pend(); epilogue(pend_nr, pend_buf, pend_slot); }
        pend = true;
        pend_nr = nr; pend_buf = buf; pend_slot = slot;
        pend_par = (rel >> 1) & 1;
    }
    if (pend) { wait_pend(); epilogue(pend_nr, pend_buf, pend_slot); }

    __syncthreads();
    if (t == 0) {
        asm volatile("mbarrier.inval.shared.b64 [%0];" :: "r"(s_ctrl + 8) : "memory");
        asm volatile("mbarrier.inval.shared.b64 [%0];" :: "r"(s_ctrl + 16) : "memory");
    }
    __syncthreads();
    if (wid == 0) {
        asm volatile("tcgen05.dealloc.cta_group::1.sync.aligned.b32 %0, %1;"
                     :: "r"(tmem), "r"(256u));
    }
    // Reset bucket counts for the next invocation (replaces the k_reset
    // launch). Safe: all 152 CTAs are resident in wave 1 and read g_count in
    // their first microsecond; CTA 0 reaches this point only after its full
    // tile loop. First invocation relies on static zero-init.
    if (blockIdx.x == 0 && t < NB) g_count[t] = 0;
#endif
}

// ---------------- launch -----------------------------------------------------
extern "C" void kernel_launch(void* const* d_in, const int* in_sizes, int n_in,
                              void* d_out, int out_size) {
    const float* x = (const float*)d_in[0];
    const int* atom_numbers = (const int*)d_in[1];
    const float* W = (const float*)d_in[2];
    const float* bias = (const float*)d_in[3];
    const int* atom_cases = (const int*)d_in[4];
    float* out = (float*)d_out;

    int nrows = in_sizes[1];  // B * A
    int nscatter = (nrows + 1023) / 1024;

    k_prep<<<nscatter + NE, 1024>>>(atom_numbers, atom_cases, W, out, nrows, nscatter);

    cudaFuncSetAttribute(k_gemm, cudaFuncAttributeMaxDynamicSharedMemorySize, SMEM_BYTES);
    k_gemm<<<NCTA, NT, SMEM_BYTES>>>(x, W, bias, out);
}

// round 8
// speedup vs baseline: 3.3791x; 1.3428x over previous
#include <cuda_runtime.h>
#include <cuda_bf16.h>
#include <cstdint>

#define CI 128
#define CO 128
#define NE 4
#define NB 5               // 4 experts + 1 "unmatched" bucket
#define MAXROWS (2048*128)
#define BM 128
#define NCTA 152           // persistent grid (GB300: 152 SMs)
#define NT 512             // threads per gemm CTA (16 warps)

// ---------------- scratch (__device__ globals; no dynamic alloc allowed) ----
__device__ int g_row_idx[NB][MAXROWS];
__device__ int g_count[NB];   // zero-initialized at load; re-zeroed by k_gemm tail
// Pre-swizzled SMEM-image of W[e] (transposed to [N=CO rows, K=CI cols],
// K-major SW128 blocked layout), split into bf16 hi/lo.
__device__ __align__(16) unsigned char g_wimg_hi[NE][32768];
__device__ __align__(16) unsigned char g_wimg_lo[NE][32768];

// ---------------- small helpers ---------------------------------------------
__device__ __forceinline__ uint32_t smem_u32(const void* p) {
    uint32_t a;
    asm("{ .reg .u64 t; cvta.to.shared.u64 t, %1; cvt.u32.u64 %0, t; }"
        : "=r"(a) : "l"(p));
    return a;
}
__device__ __forceinline__ uint32_t swz(uint32_t off) {   // SW128: Swizzle<3,4,3>
    return off ^ ((off >> 3) & 0x70);
}

// pairwise fp32 -> bf16 hi/lo split: h packs {lo=cvt(a), hi=cvt(b)},
// l packs residuals likewise. (cvt.rn.bf16x2.f32 %0,hi_src,lo_src)
__device__ __forceinline__ void split2(uint32_t& h, uint32_t& l, float a, float b) {
    asm("cvt.rn.bf16x2.f32 %0, %1, %2;" : "=r"(h) : "f"(b), "f"(a));
    float ra = a - __uint_as_float(h << 16);
    float rb = b - __uint_as_float(h & 0xffff0000u);
    asm("cvt.rn.bf16x2.f32 %0, %1, %2;" : "=r"(l) : "f"(rb), "f"(ra));
}

// SMEM descriptor: SW128, version=1(Blackwell), SBO=64, LBO=1 (K-major)
static __device__ __forceinline__ uint64_t make_desc(uint32_t addr) {
    const uint64_t BASE = (uint64_t(2) << 61) | (uint64_t(1) << 46) |
                          (uint64_t(64) << 32) | (uint64_t(1) << 16);
    return BASE | ((uint64_t)(addr >> 4) & 0x3FFF);
}

// idesc kind::f16: F32 accum(1<<4), a=BF16(1<<7), b=BF16(1<<10),
// N=128((128/8)<<17), M=128((128/16)<<24)
#define MMA_IDESC 0x8200490u

// Blocked-atom byte offset for element (row, col) in a [128 x 128] bf16 K-major
// SW128 tile: atoms of 8 rows x 64 cols (1024B), atom_offset = atom_row + atom_col*16.
__device__ __forceinline__ uint32_t tile_off_128r(uint32_t row, uint32_t col) {
    return ((row >> 3) + (col >> 6) * 16u) * 1024u + (row & 7u) * 128u + (col & 63u) * 2u;
}

// ---------------- fused prep: scatter(+zero) blocks + wprep blocks ------------
__global__ void __launch_bounds__(1024)
k_prep(const int* __restrict__ atom_numbers, const int* __restrict__ atom_cases,
       const float* __restrict__ W, float* __restrict__ out,
       int nrows, int nscatter) {
    if ((int)blockIdx.x >= nscatter) {
        // ---- wprep: coalesced (o fastest) reads from global W
        int e = blockIdx.x - nscatter;
        const float* We = W + (size_t)e * CI * CO;
        for (int item = threadIdx.x; item < CO * 16; item += 1024) {
            int o = item & 127;        // output channel (B row), lane-consecutive
            int kc = item >> 7;        // 8-wide K chunk
            uint32_t ph[4], pl[4];
#pragma unroll
            for (int j = 0; j < 4; j++) {
                float a = __ldg(We + (kc * 8 + 2 * j) * CO + o);
                float b = __ldg(We + (kc * 8 + 2 * j + 1) * CO + o);
                split2(ph[j], pl[j], a, b);
            }
            uint32_t s = swz(tile_off_128r(o, kc * 8));
            *(uint4*)((unsigned char*)g_wimg_hi[e] + s) =
                make_uint4(ph[0], ph[1], ph[2], ph[3]);
            *(uint4*)((unsigned char*)g_wimg_lo[e] + s) =
                make_uint4(pl[0], pl[1], pl[2], pl[3]);
        }
        return;
    }

    // ---- scatter + zero
    __shared__ int wcnt[NB][32];
    __shared__ int sbase[NB];
    int t = threadIdx.x, w = t >> 5, lane = t & 31;
    int row = blockIdx.x * 1024 + t;
    bool valid = row < nrows;
    int an = valid ? atom_numbers[row] : -1234567;
    int c0 = __ldg(atom_cases + 0), c1 = __ldg(atom_cases + 1);
    int c2 = __ldg(atom_cases + 2), c3 = __ldg(atom_cases + 3);
    int e = 4;                       // bucket 4 = unmatched (zero output)
    if (an == c0) e = 0;
    else if (an == c1) e = 1;
    else if (an == c2) e = 2;
    else if (an == c3) e = 3;
    if (!valid) e = -1;

    // Zero unmatched rows cooperatively: 32 lanes x float4 = one 512B row.
    {
        unsigned mu = __ballot_sync(0xffffffffu, e == 4);
        float4 zz = make_float4(0.f, 0.f, 0.f, 0.f);
        while (mu) {
            int b = __ffs(mu) - 1;
            mu &= mu - 1;
            int zr = __shfl_sync(0xffffffffu, row, b);
            ((float4*)out)[(size_t)zr * 32 + lane] = zz;
        }
    }

    int myrank = 0;
#pragma unroll
    for (int b = 0; b < NB; b++) {
        unsigned m = __ballot_sync(0xffffffffu, e == b);
        if (e == b) myrank = __popc(m & ((1u << lane) - 1u));
        if (lane == 0) wcnt[b][w] = __popc(m);
    }
    __syncthreads();
    if (t < NB) {
        int s = 0;
#pragma unroll
        for (int i = 0; i < 32; i++) { int v = wcnt[t][i]; wcnt[t][i] = s; s += v; }
        sbase[t] = s ? atomicAdd(&g_count[t], s) : 0;
    }
    __syncthreads();
    if (e >= 0) g_row_idx[e][sbase[e] + wcnt[e][w] + myrank] = row;
}

// ---------------- persistent pipelined grouped GEMM ---------------------------
// Double-buffered A in smem, double-buffered D in TMEM, two mbarriers,
// 4-slot row-index prefetch ring. Gather and output store are warp-contiguous
// (4 L1tex wavefronts per LDG/STG, not 32); epilogue transposes through the
// just-retired A buffer so output rows are stored as whole 512B lines.
// tcgen05: D = A_hi*B_hi + A_lo*B_hi + A_hi*B_lo (bf16 split, fp32 TMEM accum).
#define OFF_A(buf)  ((buf) * 65536u)            // A_hi at +0, A_lo at +32768
#define OFF_B_HI 131072u
#define OFF_B_LO 163840u
#define OFF_CTRL 196608u
#define OFF_IDX  197632u                        // 4 slots x 128 ints = 2KB
#define SMEM_BYTES (196608 + 1024 + 2048 + 1024)

__global__ void __launch_bounds__(NT, 1)
k_gemm(const float* __restrict__ x, const float* __restrict__ W,
       const float* __restrict__ bias, float* __restrict__ out) {
    int t = threadIdx.x;

    // Tile partition (uniform across threads)
    int c[NE], pfx[NE + 1];
    pfx[0] = 0;
#pragma unroll
    for (int e = 0; e < NE; e++) {
        c[e] = g_count[e];
        pfx[e + 1] = pfx[e] + ((c[e] + BM - 1) >> 7);
    }
    int total = pfx[NE];
    int begin = (int)((long long)total * blockIdx.x / gridDim.x);
    int end   = (int)((long long)total * (blockIdx.x + 1) / gridDim.x);

#if defined(__CUDA_ARCH__) && !defined(__CUDA_ARCH_FEAT_SM103_ALL)
    // ---------------- fallback: fp32 SIMT (JIT-safety only) ------------------
    for (int tile = begin; tile < end; tile++) {
        int e = 0;
        while (tile >= pfx[e + 1]) e++;
        int m0 = (tile - pfx[e]) * BM;
        int nr = min(BM, c[e] - m0);
        for (int idx = t; idx < nr * CO; idx += NT) {
            int m = idx >> 7, o = idx & 127;
            int grow = g_row_idx[e][m0 + m];
            const float* xr = x + (size_t)grow * CI;
            const float* wc = W + (size_t)e * CI * CO + o;
            float acc = bias[e * CO + o];
            for (int k = 0; k < CI; k++) acc += xr[k] * wc[(size_t)k * CO];
            out[(size_t)grow * CO + o] = fmaxf(acc, 0.f);
        }
    }
    __syncthreads();
    if (blockIdx.x == 0 && t < NB) g_count[t] = 0;
#else
    // ---------------- tcgen05 path -------------------------------------------
    extern __shared__ unsigned char smraw[];
    uint32_t sraw = smem_u32(smraw);
    uint32_t sbase = (sraw + 1023u) & ~1023u;          // 1024-align for SW128
    unsigned char* sm = smraw + (sbase - sraw);
    uint32_t s_ctrl = sbase + OFF_CTRL;   // [0]=tmem, [8],[16]=mbars, [64..]=bias
    int* s_idx = (int*)(sm + OFF_IDX);    // [4][BM] row-index ring

    int wid = t >> 5, lane = t & 31;

    if (wid == 0) {
        asm volatile("tcgen05.alloc.cta_group::1.sync.aligned.shared::cta.b32 [%0], %1;"
                     :: "r"(s_ctrl), "r"(256u) : "memory");
        asm volatile("tcgen05.relinquish_alloc_permit.cta_group::1.sync.aligned;");
    }
    if (t == 0) {
        asm volatile("mbarrier.init.shared.b64 [%0], %1;"
                     :: "r"(s_ctrl + 8), "r"(1u) : "memory");
        asm volatile("mbarrier.init.shared.b64 [%0], %1;"
                     :: "r"(s_ctrl + 16), "r"(1u) : "memory");
    }

    // Prefetch indices for tile `nt` into ring slot nt&3 (threads 0..127).
    auto prefetch_idx = [&](int nt) {
        if (nt >= end || t >= BM) return;
        int e2 = 0;
        while (nt >= pfx[e2 + 1]) e2++;
        int m02 = (nt - pfx[e2]) * BM;
        int nr2 = min(BM, c[e2] - m02);
        int v = (t < nr2) ? __ldg(&g_row_idx[e2][m02 + t]) : 0;
        s_idx[(nt & 3) * BM + t] = v;
    };
    prefetch_idx(begin);
    __syncthreads();
    uint32_t tmem;
    asm volatile("ld.shared.b32 %0, [%1];" : "=r"(tmem) : "r"(s_ctrl));

    uint64_t dbh = make_desc(sbase + OFF_B_HI);
    uint64_t dbl = make_desc(sbase + OFF_B_LO);

    // pending-tile state
    bool pend = false;
    int pend_nr = 0, pend_buf = 0, pend_par = 0, pend_slot = 0;

    // epilogue(t-1): LDTM -> bias+relu -> staged smem transpose (into the
    // retired A[ebuf] region) -> contiguous 512B row stores.
    auto epilogue = [&](int enr, int ebuf, int eslot) {
        unsigned char* stage = sm + OFF_A(ebuf);   // MMA(ebuf) done; region free
        {
            int m = (wid & 3) * 32 + lane;
            int cb = wid >> 2;
            const float* bsm = (const float*)(sm + OFF_CTRL + 64) + cb * 32;
            uint32_t td = tmem + (uint32_t)ebuf * 128u + (uint32_t)cb * 32u;
            uint32_t d[32];
            asm volatile(
                "tcgen05.ld.sync.aligned.32x32b.x32.b32 "
                "{%0, %1, %2, %3, %4, %5, %6, %7, "
                " %8, %9, %10, %11, %12, %13, %14, %15, "
                " %16, %17, %18, %19, %20, %21, %22, %23, "
                " %24, %25, %26, %27, %28, %29, %30, %31}, [%32];"
                : "=r"(d[0]),  "=r"(d[1]),  "=r"(d[2]),  "=r"(d[3]),
                  "=r"(d[4]),  "=r"(d[5]),  "=r"(d[6]),  "=r"(d[7]),
                  "=r"(d[8]),  "=r"(d[9]),  "=r"(d[10]), "=r"(d[11]),
                  "=r"(d[12]), "=r"(d[13]), "=r"(d[14]), "=r"(d[15]),
                  "=r"(d[16]), "=r"(d[17]), "=r"(d[18]), "=r"(d[19]),
                  "=r"(d[20]), "=r"(d[21]), "=r"(d[22]), "=r"(d[23]),
                  "=r"(d[24]), "=r"(d[25]), "=r"(d[26]), "=r"(d[27]),
                  "=r"(d[28]), "=r"(d[29]), "=r"(d[30]), "=r"(d[31])
                : "r"(td));
            asm volatile("tcgen05.wait::ld.sync.aligned;" ::: "memory");
#pragma unroll
            for (int j = 0; j < 32; j += 4) {
                float4 v;
                v.x = fmaxf(__uint_as_float(d[j + 0]) + bsm[j + 0], 0.f);
                v.y = fmaxf(__uint_as_float(d[j + 1]) + bsm[j + 1], 0.f);
                v.z = fmaxf(__uint_as_float(d[j + 2]) + bsm[j + 2], 0.f);
                v.w = fmaxf(__uint_as_float(d[j + 3]) + bsm[j + 3], 0.f);
                // xor-swizzled 16B chunk: logical chunk cb*8+(j>>2), phys low3 ^= m
                int chunk = cb * 8 + ((j >> 2) ^ (m & 7));
                *(float4*)(stage + m * 512 + chunk * 16) = v;
            }
        }
        __syncthreads();
        // Phase 2: warp wid stores rows wid*8..wid*8+7 as contiguous 512B rows
#pragma unroll
        for (int r8 = 0; r8 < 8; r8++) {
            int m = wid * 8 + r8;
            if (m < enr) {
                int grow = s_idx[eslot * BM + m];
                int chunk = (lane & ~7) | ((lane & 7) ^ (m & 7));
                float4 v = *(const float4*)(stage + m * 512 + chunk * 16);
                *(float4*)(out + (size_t)grow * CO + lane * 4) = v;
            }
        }
        __syncthreads();   // staging region reused by next gather
    };
    auto wait_pend = [&]() {
        uint32_t mb = s_ctrl + 8 + 8 * (uint32_t)pend_buf;
        uint32_t done = 0;
        while (!done) {
            asm volatile(
                "{\n\t.reg .pred p;\n\t"
                "mbarrier.try_wait.parity.acquire.cta.shared::cta.b64 p, [%1], %2, 0x989680;\n\t"
                "selp.b32 %0, 1, 0, p;\n\t}"
                : "=r"(done) : "r"(mb), "r"((uint32_t)pend_par) : "memory");
        }
        asm volatile("tcgen05.fence::after_thread_sync;" ::: "memory");
    };

    int cur_e = -1;
    for (int tile = begin; tile < end; tile++) {
        int e = 0;
        while (tile >= pfx[e + 1]) e++;
        int m0 = (tile - pfx[e]) * BM;
        int nr = min(BM, c[e] - m0);
        int rel = tile - begin;
        int buf = rel & 1;
        int slot = tile & 3;

        // Expert change: drain pending MMA (it reads B), then reload B + bias
        if (e != cur_e) {
            if (pend) { wait_pend(); epilogue(pend_nr, pend_buf, pend_slot); pend = false; }
            const uint4* gh = (const uint4*)g_wimg_hi[e];
            const uint4* gl = (const uint4*)g_wimg_lo[e];
            uint4* bh = (uint4*)(sm + OFF_B_HI);
            uint4* bl = (uint4*)(sm + OFF_B_LO);
#pragma unroll
            for (int i = 0; i < 4; i++) {
                bh[t + i * NT] = gh[t + i * NT];
                bl[t + i * NT] = gl[t + i * NT];
            }
            if (t < CO) ((float*)(sm + OFF_CTRL + 64))[t] = bias[e * CO + t];
            cur_e = e;
        }

        // Gather + split-convert into A[buf]: warp owns 8 whole rows; lane l
        // reads float4 l of each row (contiguous 512B per LDG -> 4 wavefronts).
        // Invalid rows (>= nr) read row index 0: finite garbage, never stored.
        {
            int base_row = wid * 8;
            int grows[8];
            float4 f[8];
#pragma unroll
            for (int r8 = 0; r8 < 8; r8++)
                grows[r8] = s_idx[slot * BM + base_row + r8];
#pragma unroll
            for (int r8 = 0; r8 < 8; r8++)
                f[r8] = ((const float4*)(x + (size_t)grows[r8] * CI))[lane];
            unsigned char* ah = sm + OFF_A(buf);
            unsigned char* al = ah + 32768;
#pragma unroll
            for (int r8 = 0; r8 < 8; r8++) {
                int row = base_row + r8;
                uint2 vh, vl;
                split2(vh.x, vl.x, f[r8].x, f[r8].y);
                split2(vh.y, vl.y, f[r8].z, f[r8].w);
                uint32_t off = ((uint32_t)(row >> 3) + (uint32_t)(lane >> 4) * 16u) * 1024u +
                               (row & 7u) * 128u + (uint32_t)(lane & 15u) * 8u;
                uint32_t s = swz(off);
                *(uint2*)(ah + s) = vh;
                *(uint2*)(al + s) = vl;
            }
        }

        // Prefetch next tile's indices (slot (tile+1)&3)
        prefetch_idx(tile + 1);

        asm volatile("fence.proxy.async.shared::cta;" ::: "memory");
        __syncthreads();

        if (t == 0) {
            uint64_t dah = make_desc(sbase + OFF_A(buf));
            uint64_t dal = make_desc(sbase + OFF_A(buf) + 32768u);
            uint64_t ta[3] = {dah, dal, dah};
            uint64_t tb[3] = {dbh, dbh, dbl};
            uint32_t td = tmem + (uint32_t)buf * 128u;
            uint32_t en = 0;
#pragma unroll
            for (int term = 0; term < 3; term++) {
#pragma unroll
                for (int k = 0; k < 8; k++) {
                    uint64_t off = (uint64_t)((k >> 2) * 1024 + (k & 3) * 2);
                    asm volatile(
                        "{\n\t.reg .pred p;\n\t"
                        "setp.ne.u32 p, %4, 0;\n\t"
                        "tcgen05.mma.cta_group::1.kind::f16 [%0], %1, %2, %3, {%5, %5, %5, %5}, p;\n\t}"
                        :: "r"(td), "l"(ta[term] + off), "l"(tb[term] + off),
                           "r"(MMA_IDESC), "r"(en), "r"(0u) : "memory");
                    en = 1;
                }
            }
            asm volatile(
                "tcgen05.commit.cta_group::1.mbarrier::arrive::one.shared::cluster.b64 [%0];"
                :: "r"(s_ctrl + 8 + 8 * (uint32_t)buf) : "memory");
        }

        // Overlap: wait + epilogue the PREVIOUS tile while this MMA runs
        if (pend) { wait_pend(); epilogue(pend_nr, pend_buf, pend_slot); }
        pend = true;
        pend_nr = nr; pend_buf = buf; pend_slot = slot;
        pend_par = (rel >> 1) & 1;
    }
    if (pend) { wait_pend(); epilogue(pend_nr, pend_buf, pend_slot); }

    __syncthreads();
    if (t == 0) {
        asm volatile("mbarrier.inval.shared.b64 [%0];" :: "r"(s_ctrl + 8) : "memory");
        asm volatile("mbarrier.inval.shared.b64 [%0];" :: "r"(s_ctrl + 16) : "memory");
    }
    __syncthreads();
    if (wid == 0) {
        asm volatile("tcgen05.dealloc.cta_group::1.sync.aligned.b32 %0, %1;"
                     :: "r"(tmem), "r"(256u));
    }
    // Reset bucket counts for the next invocation (replaces a k_reset launch).
    if (blockIdx.x == 0 && t < NB) g_count[t] = 0;
#endif
}

// ---------------- launch -----------------------------------------------------
extern "C" void kernel_launch(void* const* d_in, const int* in_sizes, int n_in,
                              void* d_out, int out_size) {
    const float* x = (const float*)d_in[0];
    const int* atom_numbers = (const int*)d_in[1];
    const float* W = (const float*)d_in[2];
    const float* bias = (const float*)d_in[3];
    const int* atom_cases = (const int*)d_in[4];
    float* out = (float*)d_out;

    int nrows = in_sizes[1];  // B * A
    int nscatter = (nrows + 1023) / 1024;

    k_prep<<<nscatter + NE, 1024>>>(atom_numbers, atom_cases, W, out, nrows, nscatter);

    cudaFuncSetAttribute(k_gemm, cudaFuncAttributeMaxDynamicSharedMemorySize, SMEM_BYTES);
    k_gemm<<<NCTA, NT, SMEM_BYTES>>>(x, W, bias, out);
}

// round 10
// speedup vs baseline: 3.7414x; 1.1072x over previous
#include <cuda_runtime.h>
#include <cuda_bf16.h>
#include <cstdint>

#define CI 128
#define CO 128
#define NE 4
#define NB 5               // 4 experts + 1 "unmatched" bucket
#define MAXROWS (2048*128)
#define BM 128
#define NCTA 152           // persistent grid (GB300: 152 SMs)
#define NT 512             // 8 producer warps + 8 consumer warps

// ---------------- scratch (__device__ globals; no dynamic alloc allowed) ----
__device__ int g_row_idx[NB][MAXROWS];
__device__ int g_count[NB];   // zero-initialized at load; re-zeroed by k_gemm tail
__device__ __align__(16) unsigned char g_wimg_hi[NE][32768];
__device__ __align__(16) unsigned char g_wimg_lo[NE][32768];

// ---------------- small helpers ---------------------------------------------
__device__ __forceinline__ uint32_t smem_u32(const void* p) {
    uint32_t a;
    asm("{ .reg .u64 t; cvta.to.shared.u64 t, %1; cvt.u32.u64 %0, t; }"
        : "=r"(a) : "l"(p));
    return a;
}
__device__ __forceinline__ uint32_t swz(uint32_t off) {   // SW128: Swizzle<3,4,3>
    return off ^ ((off >> 3) & 0x70);
}
__device__ __forceinline__ void split2(uint32_t& h, uint32_t& l, float a, float b) {
    asm("cvt.rn.bf16x2.f32 %0, %1, %2;" : "=r"(h) : "f"(b), "f"(a));
    float ra = a - __uint_as_float(h << 16);
    float rb = b - __uint_as_float(h & 0xffff0000u);
    asm("cvt.rn.bf16x2.f32 %0, %1, %2;" : "=r"(l) : "f"(rb), "f"(ra));
}
static __device__ __forceinline__ uint64_t make_desc(uint32_t addr) {
    const uint64_t BASE = (uint64_t(2) << 61) | (uint64_t(1) << 46) |
                          (uint64_t(64) << 32) | (uint64_t(1) << 16);
    return BASE | ((uint64_t)(addr >> 4) & 0x3FFF);
}
#define MMA_IDESC 0x8200490u
__device__ __forceinline__ uint32_t tile_off_128r(uint32_t row, uint32_t col) {
    return ((row >> 3) + (col >> 6) * 16u) * 1024u + (row & 7u) * 128u + (col & 63u) * 2u;
}
__device__ __forceinline__ void mbar_wait(uint32_t mb, uint32_t par) {
    uint32_t done = 0;
    while (!done) {
        asm volatile(
            "{\n\t.reg .pred p;\n\t"
            "mbarrier.try_wait.parity.acquire.cta.shared::cta.b64 p, [%1], %2, 0x989680;\n\t"
            "selp.b32 %0, 1, 0, p;\n\t}"
            : "=r"(done) : "r"(mb), "r"(par) : "memory");
    }
}

// ---------------- fused prep: scatter(+zero) blocks + wprep blocks ------------
__global__ void __launch_bounds__(1024)
k_prep(const int* __restrict__ atom_numbers, const int* __restrict__ atom_cases,
       const float* __restrict__ W, float* __restrict__ out,
       int nrows, int nscatter) {
    if ((int)blockIdx.x >= nscatter) {
        int e = blockIdx.x - nscatter;
        const float* We = W + (size_t)e * CI * CO;
        for (int item = threadIdx.x; item < CO * 16; item += 1024) {
            int o = item & 127;
            int kc = item >> 7;
            uint32_t ph[4], pl[4];
#pragma unroll
            for (int j = 0; j < 4; j++) {
                float a = __ldg(We + (kc * 8 + 2 * j) * CO + o);
                float b = __ldg(We + (kc * 8 + 2 * j + 1) * CO + o);
                split2(ph[j], pl[j], a, b);
            }
            uint32_t s = swz(tile_off_128r(o, kc * 8));
            *(uint4*)((unsigned char*)g_wimg_hi[e] + s) =
                make_uint4(ph[0], ph[1], ph[2], ph[3]);
            *(uint4*)((unsigned char*)g_wimg_lo[e] + s) =
                make_uint4(pl[0], pl[1], pl[2], pl[3]);
        }
        return;
    }

    __shared__ int wcnt[NB][32];
    __shared__ int sbase[NB];
    int t = threadIdx.x, w = t >> 5, lane = t & 31;
    int row = blockIdx.x * 1024 + t;
    bool valid = row < nrows;
    int an = valid ? atom_numbers[row] : -1234567;
    int c0 = __ldg(atom_cases + 0), c1 = __ldg(atom_cases + 1);
    int c2 = __ldg(atom_cases + 2), c3 = __ldg(atom_cases + 3);
    int e = 4;
    if (an == c0) e = 0;
    else if (an == c1) e = 1;
    else if (an == c2) e = 2;
    else if (an == c3) e = 3;
    if (!valid) e = -1;

    {   // zero unmatched rows: 32 lanes x float4 = one contiguous 512B row
        unsigned mu = __ballot_sync(0xffffffffu, e == 4);
        float4 zz = make_float4(0.f, 0.f, 0.f, 0.f);
        while (mu) {
            int b = __ffs(mu) - 1;
            mu &= mu - 1;
            int zr = __shfl_sync(0xffffffffu, row, b);
            ((float4*)out)[(size_t)zr * 32 + lane] = zz;
        }
    }

    int myrank = 0;
#pragma unroll
    for (int b = 0; b < NB; b++) {
        unsigned m = __ballot_sync(0xffffffffu, e == b);
        if (e == b) myrank = __popc(m & ((1u << lane) - 1u));
        if (lane == 0) wcnt[b][w] = __popc(m);
    }
    __syncthreads();
    if (t < NB) {
        int s = 0;
#pragma unroll
        for (int i = 0; i < 32; i++) { int v = wcnt[t][i]; wcnt[t][i] = s; s += v; }
        sbase[t] = s ? atomicAdd(&g_count[t], s) : 0;
    }
    __syncthreads();
    if (e >= 0) g_row_idx[e][sbase[e] + wcnt[e][w] + myrank] = row;
}

// ---------------- warp-specialized persistent grouped GEMM --------------------
// Warps 0-7  (producers): gather+convert rows into A[buf], then t0 issues MMA.
// Warps 8-15 (consumers): wait MMA, LDTM, +bias/relu, smem-transpose, store.
// Rings: A[2] in smem (64KB each), D[2] in TMEM (128 cols each).
// mma_mbar[b] (count 1): MMA(tile) commit. Completion for tile rel lands on
//   phase (rel>>1)&1. Gates: consumer epilogue(rel); producer A-refill (rel+2);
//   producer B reload (expert change waits MMA(rel-1)).
// epi_mbar[b] (count 256): consumers done reading D[b]; gates MMA issue (rel+2).
#define OFF_A(buf)  ((buf) * 65536u)            // A_hi at +0, A_lo at +32768
#define OFF_B_HI 131072u
#define OFF_B_LO 163840u
#define OFF_STAGE 196608u                        // 32KB transpose stage (consumers)
#define OFF_CTRL 229376u                         // [0]=tmem [8,16]=mma [24,32]=epi [64..]=bias
#define SMEM_BYTES (229376 + 1024 + 1024)

__global__ void __launch_bounds__(NT, 1)
k_gemm(const float* __restrict__ x, const float* __restrict__ W,
       const float* __restrict__ bias, float* __restrict__ out) {
    int t = threadIdx.x;

    int c[NE], pfx[NE + 1];
    pfx[0] = 0;
#pragma unroll
    for (int e = 0; e < NE; e++) {
        c[e] = g_count[e];
        pfx[e + 1] = pfx[e] + ((c[e] + BM - 1) >> 7);
    }
    int total = pfx[NE];
    int begin = (int)((long long)total * blockIdx.x / gridDim.x);
    int end   = (int)((long long)total * (blockIdx.x + 1) / gridDim.x);

#if defined(__CUDA_ARCH__) && !defined(__CUDA_ARCH_FEAT_SM103_ALL)
    // ---------------- fallback: fp32 SIMT (JIT-safety only) ------------------
    for (int tile = begin; tile < end; tile++) {
        int e = 0;
        while (tile >= pfx[e + 1]) e++;
        int m0 = (tile - pfx[e]) * BM;
        int nr = min(BM, c[e] - m0);
        for (int idx = t; idx < nr * CO; idx += NT) {
            int m = idx >> 7, o = idx & 127;
            int grow = g_row_idx[e][m0 + m];
            const float* xr = x + (size_t)grow * CI;
            const float* wc = W + (size_t)e * CI * CO + o;
            float acc = bias[e * CO + o];
            for (int k = 0; k < CI; k++) acc += xr[k] * wc[(size_t)k * CO];
            out[(size_t)grow * CO + o] = fmaxf(acc, 0.f);
        }
    }
    __syncthreads();
    if (blockIdx.x == 0 && t < NB) g_count[t] = 0;
#else
    // ---------------- tcgen05 path -------------------------------------------
    extern __shared__ unsigned char smraw[];
    uint32_t sraw = smem_u32(smraw);
    uint32_t sbase = (sraw + 1023u) & ~1023u;
    unsigned char* sm = smraw + (sbase - sraw);
    uint32_t s_ctrl = sbase + OFF_CTRL;

    int wid = t >> 5, lane = t & 31;

    if (wid == 0) {
        asm volatile("tcgen05.alloc.cta_group::1.sync.aligned.shared::cta.b32 [%0], %1;"
                     :: "r"(s_ctrl), "r"(256u) : "memory");
        asm volatile("tcgen05.relinquish_alloc_permit.cta_group::1.sync.aligned;");
    }
    if (t == 0) {
        asm volatile("mbarrier.init.shared.b64 [%0], %1;" :: "r"(s_ctrl + 8), "r"(1u) : "memory");
        asm volatile("mbarrier.init.shared.b64 [%0], %1;" :: "r"(s_ctrl + 16), "r"(1u) : "memory");
        asm volatile("mbarrier.init.shared.b64 [%0], %1;" :: "r"(s_ctrl + 24), "r"(256u) : "memory");
        asm volatile("mbarrier.init.shared.b64 [%0], %1;" :: "r"(s_ctrl + 32), "r"(256u) : "memory");
    }
    __syncthreads();
    uint32_t tmem;
    asm volatile("ld.shared.b32 %0, [%1];" : "=r"(tmem) : "r"(s_ctrl));

    if (wid < 8) {
        // ======================= PRODUCER (threads 0..255) ===================
        uint64_t dbh = make_desc(sbase + OFF_B_HI);
        uint64_t dbl = make_desc(sbase + OFF_B_LO);
        int cur_e = -1;
        for (int tile = begin; tile < end; tile++) {
            int e = 0;
            while (tile >= pfx[e + 1]) e++;
            int m0 = (tile - pfx[e]) * BM;
            int nr = min(BM, c[e] - m0);
            int rel = tile - begin;
            int buf = rel & 1;
            uint32_t p2 = (uint32_t)(((rel - 2) >> 1) & 1);

            // A[buf] free? (MMA of tile-2 must have read it)
            if (rel >= 2) mbar_wait(s_ctrl + 8 + 8u * (uint32_t)buf, p2);

            // Expert change: B is read by MMA(tile-1) too -> wait it, reload B
            if (e != cur_e) {
                if (rel >= 1) {
                    mbar_wait(s_ctrl + 8 + 8u * (uint32_t)((rel - 1) & 1),
                              (uint32_t)(((rel - 1) >> 1) & 1));
                }
                const uint4* gh = (const uint4*)g_wimg_hi[e];
                const uint4* gl = (const uint4*)g_wimg_lo[e];
                uint4* bh = (uint4*)(sm + OFF_B_HI);
                uint4* bl = (uint4*)(sm + OFF_B_LO);
                // 32KB per image = 2048 uint4 = 8 iters x 256 producer threads
#pragma unroll
                for (int i = 0; i < 8; i++) {
                    bh[t + i * 256] = gh[t + i * 256];
                    bl[t + i * 256] = gl[t + i * 256];
                }
                cur_e = e;
            }

            // Gather 16 rows per warp; lane l reads float4 l (contiguous 512B)
            {
                int rbase = wid * 16;
                int gidx = 0;
                if (lane < 16) {
                    int rr = rbase + lane;
                    gidx = (rr < nr) ? __ldg(&g_row_idx[e][m0 + rr]) : 0;
                }
                unsigned char* ah = sm + OFF_A(buf);
                unsigned char* al = ah + 32768;
#pragma unroll
                for (int grp = 0; grp < 2; grp++) {
                    int rws[8];
                    float4 f[8];
#pragma unroll
                    for (int r = 0; r < 8; r++)
                        rws[r] = __shfl_sync(0xffffffffu, gidx, grp * 8 + r);
#pragma unroll
                    for (int r = 0; r < 8; r++)
                        f[r] = ((const float4*)(x + (size_t)rws[r] * CI))[lane];
#pragma unroll
                    for (int r = 0; r < 8; r++) {
                        int row = rbase + grp * 8 + r;
                        uint2 vh, vl;
                        split2(vh.x, vl.x, f[r].x, f[r].y);
                        split2(vh.y, vl.y, f[r].z, f[r].w);
                        uint32_t off = ((uint32_t)(row >> 3) + (uint32_t)(lane >> 4) * 16u) * 1024u +
                                       (row & 7u) * 128u + (uint32_t)(lane & 15u) * 8u;
                        uint32_t s = swz(off);
                        *(uint2*)(ah + s) = vh;
                        *(uint2*)(al + s) = vl;
                    }
                }
            }

            asm volatile("fence.proxy.async.shared::cta;" ::: "memory");
            asm volatile("bar.sync 1, 256;" ::: "memory");

            if (t == 0) {
                // D[buf] free? (consumers must have read tile-2's D)
                if (rel >= 2) mbar_wait(s_ctrl + 24 + 8u * (uint32_t)buf, p2);
                uint64_t dah = make_desc(sbase + OFF_A(buf));
                uint64_t dal = make_desc(sbase + OFF_A(buf) + 32768u);
                uint64_t ta[3] = {dah, dal, dah};
                uint64_t tb[3] = {dbh, dbh, dbl};
                uint32_t td = tmem + (uint32_t)buf * 128u;
                uint32_t en = 0;
#pragma unroll
                for (int term = 0; term < 3; term++) {
#pragma unroll
                    for (int k = 0; k < 8; k++) {
                        uint64_t off = (uint64_t)((k >> 2) * 1024 + (k & 3) * 2);
                        asm volatile(
                            "{\n\t.reg .pred p;\n\t"
                            "setp.ne.u32 p, %4, 0;\n\t"
                            "tcgen05.mma.cta_group::1.kind::f16 [%0], %1, %2, %3, {%5, %5, %5, %5}, p;\n\t}"
                            :: "r"(td), "l"(ta[term] + off), "l"(tb[term] + off),
                               "r"(MMA_IDESC), "r"(en), "r"(0u) : "memory");
                        en = 1;
                    }
                }
                asm volatile(
                    "tcgen05.commit.cta_group::1.mbarrier::arrive::one.shared::cluster.b64 [%0];"
                    :: "r"(s_ctrl + 8 + 8u * (uint32_t)buf) : "memory");
            }
        }
    } else {
        // ======================= CONSUMER (threads 256..511) =================
        int cw = wid - 8, sub = wid & 3, ch = (wid >> 2) & 1;
        float* stg = (float*)(sm + OFF_STAGE);
        const float* bsm = (const float*)(sm + OFF_CTRL + 64);
        int cur_e = -1;
        for (int tile = begin; tile < end; tile++) {
            int e = 0;
            while (tile >= pfx[e + 1]) e++;
            int m0 = (tile - pfx[e]) * BM;
            int nr = min(BM, c[e] - m0);
            int rel = tile - begin;
            int buf = rel & 1;
            uint32_t par = (uint32_t)((rel >> 1) & 1);

            // bias refresh on expert change (uniform across consumer warps)
            if (e != cur_e) {
                int ct = t - 256;
                if (ct < CO) ((float*)(sm + OFF_CTRL + 64))[ct] = bias[e * CO + ct];
                asm volatile("bar.sync 2, 256;" ::: "memory");
                cur_e = e;
            }

            // store-row indices: lanes 0..15 hold rows h*64 + cw*8 + r
            int sidx = 0;
            if (lane < 16) {
                int mrow = (lane >> 3) * 64 + cw * 8 + (lane & 7);
                sidx = (mrow < nr) ? __ldg(&g_row_idx[e][m0 + mrow]) : 0;
            }

            mbar_wait(s_ctrl + 8 + 8u * (uint32_t)buf, par);
            asm volatile("tcgen05.fence::after_thread_sync;" ::: "memory");

#pragma unroll
            for (int h = 0; h < 2; h++) {
                if ((sub >> 1) == h) {
                    int sr = (sub & 1) * 32 + lane;   // row within this half
                    uint32_t td = tmem + (uint32_t)buf * 128u + (uint32_t)ch * 64u;
#pragma unroll
                    for (int b = 0; b < 2; b++) {
                        uint32_t d[32];
                        asm volatile(
                            "tcgen05.ld.sync.aligned.32x32b.x32.b32 "
                            "{%0, %1, %2, %3, %4, %5, %6, %7, "
                            " %8, %9, %10, %11, %12, %13, %14, %15, "
                            " %16, %17, %18, %19, %20, %21, %22, %23, "
                            " %24, %25, %26, %27, %28, %29, %30, %31}, [%32];"
                            : "=r"(d[0]),  "=r"(d[1]),  "=r"(d[2]),  "=r"(d[3]),
                              "=r"(d[4]),  "=r"(d[5]),  "=r"(d[6]),  "=r"(d[7]),
                              "=r"(d[8]),  "=r"(d[9]),  "=r"(d[10]), "=r"(d[11]),
                              "=r"(d[12]), "=r"(d[13]), "=r"(d[14]), "=r"(d[15]),
                              "=r"(d[16]), "=r"(d[17]), "=r"(d[18]), "=r"(d[19]),
                              "=r"(d[20]), "=r"(d[21]), "=r"(d[22]), "=r"(d[23]),
                              "=r"(d[24]), "=r"(d[25]), "=r"(d[26]), "=r"(d[27]),
                              "=r"(d[28]), "=r"(d[29]), "=r"(d[30]), "=r"(d[31])
                            : "r"(td + (uint32_t)b * 32u));
                        asm volatile("tcgen05.wait::ld.sync.aligned;" ::: "memory");
#pragma unroll
                        for (int j = 0; j < 32; j += 4) {
                            int col = ch * 64 + b * 32 + j;
                            float4 v;
                            v.x = fmaxf(__uint_as_float(d[j + 0]) + bsm[col + 0], 0.f);
                            v.y = fmaxf(__uint_as_float(d[j + 1]) + bsm[col + 1], 0.f);
                            v.z = fmaxf(__uint_as_float(d[j + 2]) + bsm[col + 2], 0.f);
                            v.w = fmaxf(__uint_as_float(d[j + 3]) + bsm[col + 3], 0.f);
                            int phys = ch * 16 + (((b * 8 + (j >> 2)) ^ sr) & 15);
                            *(float4*)((unsigned char*)stg + sr * 512 + phys * 16) = v;
                        }
                    }
                    // D[buf] reads done for this thread -> release to producer
                    asm volatile("mbarrier.arrive.shared.b64 _, [%0];"
                                 :: "r"(s_ctrl + 24 + 8u * (uint32_t)buf) : "memory");
                }
                asm volatile("bar.sync 2, 256;" ::: "memory");
                // store: all 8 consumer warps, rows h*64+cw*8 .. +7, 512B/row
#pragma unroll
                for (int r8 = 0; r8 < 8; r8++) {
                    int m = h * 64 + cw * 8 + r8;
                    int grow = __shfl_sync(0xffffffffu, sidx, h * 8 + r8);
                    if (m < nr) {
                        int srm = cw * 8 + r8;
                        int phys = (lane & 16) | ((lane ^ srm) & 15);
                        float4 v = *(const float4*)((unsigned char*)stg + srm * 512 + phys * 16);
                        *(float4*)(out + (size_t)grow * CO + lane * 4) = v;
                    }
                }
                asm volatile("bar.sync 2, 256;" ::: "memory");
            }
        }
    }

    __syncthreads();
    if (t == 0) {
        asm volatile("mbarrier.inval.shared.b64 [%0];" :: "r"(s_ctrl + 8) : "memory");
        asm volatile("mbarrier.inval.shared.b64 [%0];" :: "r"(s_ctrl + 16) : "memory");
        asm volatile("mbarrier.inval.shared.b64 [%0];" :: "r"(s_ctrl + 24) : "memory");
        asm volatile("mbarrier.inval.shared.b64 [%0];" :: "r"(s_ctrl + 32) : "memory");
    }
    __syncthreads();
    if (wid == 0) {
        asm volatile("tcgen05.dealloc.cta_group::1.sync.aligned.b32 %0, %1;"
                     :: "r"(tmem), "r"(256u));
    }
    if (blockIdx.x == 0 && t < NB) g_count[t] = 0;
#endif
}

// ---------------- launch -----------------------------------------------------
extern "C" void kernel_launch(void* const* d_in, const int* in_sizes, int n_in,
                              void* d_out, int out_size) {
    const float* x = (const float*)d_in[0];
    const int* atom_numbers = (const int*)d_in[1];
    const float* W = (const float*)d_in[2];
    const float* bias = (const float*)d_in[3];
    const int* atom_cases = (const int*)d_in[4];
    float* out = (float*)d_out;

    int nrows = in_sizes[1];  // B * A
    int nscatter = (nrows + 1023) / 1024;

    k_prep<<<nscatter + NE, 1024>>>(atom_numbers, atom_cases, W, out, nrows, nscatter);

    cudaFuncSetAttribute(k_gemm, cudaFuncAttributeMaxDynamicSharedMemorySize, SMEM_BYTES);
    k_gemm<<<NCTA, NT, SMEM_BYTES>>>(x, W, bias, out);
}

// round 11
// speedup vs baseline: 3.8839x; 1.0381x over previous
#include <cuda_runtime.h>
#include <cuda_bf16.h>
#include <cstdint>

#define CI 128
#define CO 128
#define NE 4
#define NB 5               // 4 experts + 1 "unmatched" bucket
#define MAXROWS (2048*128)
#define BM 128
#define NCTA 152           // persistent grid (GB300: 152 SMs)
#define NT 512             // 8 producer warps + 8 consumer warps

// ---------------- scratch (__device__ globals; no dynamic alloc allowed) ----
__device__ int g_row_idx[NB][MAXROWS];
__device__ int g_count[NB];   // zero-initialized at load; re-zeroed by k_gemm tail
__device__ __align__(16) unsigned char g_wimg_hi[NE][32768];
__device__ __align__(16) unsigned char g_wimg_lo[NE][32768];

// ---------------- small helpers ---------------------------------------------
__device__ __forceinline__ uint32_t smem_u32(const void* p) {
    uint32_t a;
    asm("{ .reg .u64 t; cvta.to.shared.u64 t, %1; cvt.u32.u64 %0, t; }"
        : "=r"(a) : "l"(p));
    return a;
}
__device__ __forceinline__ uint32_t swz(uint32_t off) {   // SW128: Swizzle<3,4,3>
    return off ^ ((off >> 3) & 0x70);
}
__device__ __forceinline__ void split2(uint32_t& h, uint32_t& l, float a, float b) {
    asm("cvt.rn.bf16x2.f32 %0, %1, %2;" : "=r"(h) : "f"(b), "f"(a));
    float ra = a - __uint_as_float(h << 16);
    float rb = b - __uint_as_float(h & 0xffff0000u);
    asm("cvt.rn.bf16x2.f32 %0, %1, %2;" : "=r"(l) : "f"(rb), "f"(ra));
}
static __device__ __forceinline__ uint64_t make_desc(uint32_t addr) {
    const uint64_t BASE = (uint64_t(2) << 61) | (uint64_t(1) << 46) |
                          (uint64_t(64) << 32) | (uint64_t(1) << 16);
    return BASE | ((uint64_t)(addr >> 4) & 0x3FFF);
}
#define MMA_IDESC 0x8200490u          // f32 accum, bf16 a/b, M=128, N=128
__device__ __forceinline__ uint32_t tile_off_128r(uint32_t row, uint32_t col) {
    return ((row >> 3) + (col >> 6) * 16u) * 1024u + (row & 7u) * 128u + (col & 63u) * 2u;
}
__device__ __forceinline__ void mbar_wait(uint32_t mb, uint32_t par) {
    uint32_t done = 0;
    while (!done) {
        asm volatile(
            "{\n\t.reg .pred p;\n\t"
            "mbarrier.try_wait.parity.acquire.cta.shared::cta.b64 p, [%1], %2, 0x989680;\n\t"
            "selp.b32 %0, 1, 0, p;\n\t}"
            : "=r"(done) : "r"(mb), "r"(par) : "memory");
    }
}

// ---------------- fused prep: scatter(+zero) blocks + wprep blocks ------------
__global__ void __launch_bounds__(1024)
k_prep(const int* __restrict__ atom_numbers, const int* __restrict__ atom_cases,
       const float* __restrict__ W, float* __restrict__ out,
       int nrows, int nscatter) {
    if ((int)blockIdx.x >= nscatter) {
        int e = blockIdx.x - nscatter;
        const float* We = W + (size_t)e * CI * CO;
        for (int item = threadIdx.x; item < CO * 16; item += 1024) {
            int o = item & 127;
            int kc = item >> 7;
            uint32_t ph[4], pl[4];
#pragma unroll
            for (int j = 0; j < 4; j++) {
                float a = __ldg(We + (kc * 8 + 2 * j) * CO + o);
                float b = __ldg(We + (kc * 8 + 2 * j + 1) * CO + o);
                split2(ph[j], pl[j], a, b);
            }
            uint32_t s = swz(tile_off_128r(o, kc * 8));
            *(uint4*)((unsigned char*)g_wimg_hi[e] + s) =
                make_uint4(ph[0], ph[1], ph[2], ph[3]);
            *(uint4*)((unsigned char*)g_wimg_lo[e] + s) =
                make_uint4(pl[0], pl[1], pl[2], pl[3]);
        }
        return;
    }

    __shared__ int wcnt[NB][32];
    __shared__ int sbase[NB];
    int t = threadIdx.x, w = t >> 5, lane = t & 31;
    int row = blockIdx.x * 1024 + t;
    bool valid = row < nrows;
    int an = valid ? atom_numbers[row] : -1234567;
    int c0 = __ldg(atom_cases + 0), c1 = __ldg(atom_cases + 1);
    int c2 = __ldg(atom_cases + 2), c3 = __ldg(atom_cases + 3);
    int e = 4;
    if (an == c0) e = 0;
    else if (an == c1) e = 1;
    else if (an == c2) e = 2;
    else if (an == c3) e = 3;
    if (!valid) e = -1;

    {   // zero unmatched rows: 32 lanes x float4 = one contiguous 512B row
        unsigned mu = __ballot_sync(0xffffffffu, e == 4);
        float4 zz = make_float4(0.f, 0.f, 0.f, 0.f);
        while (mu) {
            int b = __ffs(mu) - 1;
            mu &= mu - 1;
            int zr = __shfl_sync(0xffffffffu, row, b);
            ((float4*)out)[(size_t)zr * 32 + lane] = zz;
        }
    }

    int myrank = 0;
#pragma unroll
    for (int b = 0; b < NB; b++) {
        unsigned m = __ballot_sync(0xffffffffu, e == b);
        if (e == b) myrank = __popc(m & ((1u << lane) - 1u));
        if (lane == 0) wcnt[b][w] = __popc(m);
    }
    __syncthreads();
    if (t < NB) {
        int s = 0;
#pragma unroll
        for (int i = 0; i < 32; i++) { int v = wcnt[t][i]; wcnt[t][i] = s; s += v; }
        sbase[t] = s ? atomicAdd(&g_count[t], s) : 0;
    }
    __syncthreads();
    if (e >= 0) g_row_idx[e][sbase[e] + wcnt[e][w] + myrank] = row;
}

// ---------------- warp-specialized persistent grouped GEMM (transposed) -------
// D^T in TMEM: lanes = output channels (M=W rows), cols = gathered rows (N).
//   MMA: ta = W image descriptors, tb = x tile descriptors (roles swapped).
// Warps 0-7  (producers): gather+convert x rows into A[buf]; t0 issues MMA.
// Warps 8-15 (consumers): prefetch row idx -> wait MMA -> 2x LDTM.x32 ->
//   relu + register bias -> 64 line-contiguous STG.32 per thread-col.
// mma_mbar[b] (count 1): completion of MMA(rel) lands on phase (rel>>1)&1.
// epi_mbar[b] (count 256): consumers done reading D[b]; gates MMA(rel+2).
#define OFF_A(buf)  ((buf) * 65536u)            // x_hi at +0, x_lo at +32768
#define OFF_B_HI 131072u
#define OFF_B_LO 163840u
#define OFF_CTRL 196608u                         // [0]=tmem [8,16]=mma [24,32]=epi
#define SMEM_BYTES (196608 + 1024 + 1024)

__global__ void __launch_bounds__(NT, 1)
k_gemm(const float* __restrict__ x, const float* __restrict__ W,
       const float* __restrict__ bias, float* __restrict__ out) {
    int t = threadIdx.x;

    int c[NE], pfx[NE + 1];
    pfx[0] = 0;
#pragma unroll
    for (int e = 0; e < NE; e++) {
        c[e] = g_count[e];
        pfx[e + 1] = pfx[e] + ((c[e] + BM - 1) >> 7);
    }
    int total = pfx[NE];
    int begin = (int)((long long)total * blockIdx.x / gridDim.x);
    int end   = (int)((long long)total * (blockIdx.x + 1) / gridDim.x);

#if defined(__CUDA_ARCH__) && !defined(__CUDA_ARCH_FEAT_SM103_ALL)
    // ---------------- fallback: fp32 SIMT (JIT-safety only) ------------------
    for (int tile = begin; tile < end; tile++) {
        int e = 0;
        while (tile >= pfx[e + 1]) e++;
        int m0 = (tile - pfx[e]) * BM;
        int nr = min(BM, c[e] - m0);
        for (int idx = t; idx < nr * CO; idx += NT) {
            int m = idx >> 7, o = idx & 127;
            int grow = g_row_idx[e][m0 + m];
            const float* xr = x + (size_t)grow * CI;
            const float* wc = W + (size_t)e * CI * CO + o;
            float acc = bias[e * CO + o];
            for (int k = 0; k < CI; k++) acc += xr[k] * wc[(size_t)k * CO];
            out[(size_t)grow * CO + o] = fmaxf(acc, 0.f);
        }
    }
    __syncthreads();
    if (blockIdx.x == 0 && t < NB) g_count[t] = 0;
#else
    // ---------------- tcgen05 path -------------------------------------------
    extern __shared__ unsigned char smraw[];
    uint32_t sraw = smem_u32(smraw);
    uint32_t sbase = (sraw + 1023u) & ~1023u;
    unsigned char* sm = smraw + (sbase - sraw);
    uint32_t s_ctrl = sbase + OFF_CTRL;

    int wid = t >> 5, lane = t & 31;

    if (wid == 0) {
        asm volatile("tcgen05.alloc.cta_group::1.sync.aligned.shared::cta.b32 [%0], %1;"
                     :: "r"(s_ctrl), "r"(256u) : "memory");
        asm volatile("tcgen05.relinquish_alloc_permit.cta_group::1.sync.aligned;");
    }
    if (t == 0) {
        asm volatile("mbarrier.init.shared.b64 [%0], %1;" :: "r"(s_ctrl + 8), "r"(1u) : "memory");
        asm volatile("mbarrier.init.shared.b64 [%0], %1;" :: "r"(s_ctrl + 16), "r"(1u) : "memory");
        asm volatile("mbarrier.init.shared.b64 [%0], %1;" :: "r"(s_ctrl + 24), "r"(256u) : "memory");
        asm volatile("mbarrier.init.shared.b64 [%0], %1;" :: "r"(s_ctrl + 32), "r"(256u) : "memory");
    }
    __syncthreads();
    uint32_t tmem;
    asm volatile("ld.shared.b32 %0, [%1];" : "=r"(tmem) : "r"(s_ctrl));

    if (wid < 8) {
        // ======================= PRODUCER (threads 0..255) ===================
        uint64_t dbh = make_desc(sbase + OFF_B_HI);
        uint64_t dbl = make_desc(sbase + OFF_B_LO);
        int cur_e = -1;
        for (int tile = begin; tile < end; tile++) {
            int e = 0;
            while (tile >= pfx[e + 1]) e++;
            int m0 = (tile - pfx[e]) * BM;
            int nr = min(BM, c[e] - m0);
            int rel = tile - begin;
            int buf = rel & 1;
            uint32_t p2 = (uint32_t)(((rel - 2) >> 1) & 1);

            // A[buf] free? (MMA of tile-2 must have read it)
            if (rel >= 2) mbar_wait(s_ctrl + 8 + 8u * (uint32_t)buf, p2);

            // Expert change: W is read by MMA(tile-1) too -> wait it, reload W
            if (e != cur_e) {
                if (rel >= 1) {
                    mbar_wait(s_ctrl + 8 + 8u * (uint32_t)((rel - 1) & 1),
                              (uint32_t)(((rel - 1) >> 1) & 1));
                }
                const uint4* gh = (const uint4*)g_wimg_hi[e];
                const uint4* gl = (const uint4*)g_wimg_lo[e];
                uint4* bh = (uint4*)(sm + OFF_B_HI);
                uint4* bl = (uint4*)(sm + OFF_B_LO);
                // 32KB per image = 2048 uint4 = 8 iters x 256 producer threads
#pragma unroll
                for (int i = 0; i < 8; i++) {
                    bh[t + i * 256] = gh[t + i * 256];
                    bl[t + i * 256] = gl[t + i * 256];
                }
                cur_e = e;
            }

            // Gather 16 rows per warp; lane l reads float4 l (contiguous 512B)
            {
                int rbase = wid * 16;
                int gidx = 0;
                if (lane < 16) {
                    int rr = rbase + lane;
                    gidx = (rr < nr) ? __ldg(&g_row_idx[e][m0 + rr]) : 0;
                }
                unsigned char* ah = sm + OFF_A(buf);
                unsigned char* al = ah + 32768;
#pragma unroll
                for (int grp = 0; grp < 2; grp++) {
                    int rws[8];
                    float4 f[8];
#pragma unroll
                    for (int r = 0; r < 8; r++)
                        rws[r] = __shfl_sync(0xffffffffu, gidx, grp * 8 + r);
#pragma unroll
                    for (int r = 0; r < 8; r++)
                        f[r] = ((const float4*)(x + (size_t)rws[r] * CI))[lane];
#pragma unroll
                    for (int r = 0; r < 8; r++) {
                        int row = rbase + grp * 8 + r;
                        uint2 vh, vl;
                        split2(vh.x, vl.x, f[r].x, f[r].y);
                        split2(vh.y, vl.y, f[r].z, f[r].w);
                        uint32_t off = ((uint32_t)(row >> 3) + (uint32_t)(lane >> 4) * 16u) * 1024u +
                                       (row & 7u) * 128u + (uint32_t)(lane & 15u) * 8u;
                        uint32_t s = swz(off);
                        *(uint2*)(ah + s) = vh;
                        *(uint2*)(al + s) = vl;
                    }
                }
            }

            asm volatile("fence.proxy.async.shared::cta;" ::: "memory");
            asm volatile("bar.sync 1, 256;" ::: "memory");

            if (t == 0) {
                // D[buf] free? (consumers must have read tile-2's D)
                if (rel >= 2) mbar_wait(s_ctrl + 24 + 8u * (uint32_t)buf, p2);
                uint64_t dah = make_desc(sbase + OFF_A(buf));
                uint64_t dal = make_desc(sbase + OFF_A(buf) + 32768u);
                // transposed: A operand = W image (M=o), B operand = x tile (N=row)
                uint64_t ta[3] = {dbh, dbh, dbl};
                uint64_t tb[3] = {dah, dal, dah};
                uint32_t td = tmem + (uint32_t)buf * 128u;
                uint32_t en = 0;
#pragma unroll
                for (int term = 0; term < 3; term++) {
#pragma unroll
                    for (int k = 0; k < 8; k++) {
                        uint64_t off = (uint64_t)((k >> 2) * 1024 + (k & 3) * 2);
                        asm volatile(
                            "{\n\t.reg .pred p;\n\t"
                            "setp.ne.u32 p, %4, 0;\n\t"
                            "tcgen05.mma.cta_group::1.kind::f16 [%0], %1, %2, %3, {%5, %5, %5, %5}, p;\n\t}"
                            :: "r"(td), "l"(ta[term] + off), "l"(tb[term] + off),
                               "r"(MMA_IDESC), "r"(en), "r"(0u) : "memory");
                        en = 1;
                    }
                }
                asm volatile(
                    "tcgen05.commit.cta_group::1.mbarrier::arrive::one.shared::cluster.b64 [%0];"
                    :: "r"(s_ctrl + 8 + 8u * (uint32_t)buf) : "memory");
            }
        }
    } else {
        // ======================= CONSUMER (threads 256..511) =================
        // warp handles output channels o = sub*32+lane (TMEM lanes) for
        // row-cols ch*64 .. ch*64+63 (TMEM columns).
        int sub = wid & 3, ch = (wid >> 2) & 1;
        float breg = 0.f;
        int cur_e = -1;
        for (int tile = begin; tile < end; tile++) {
            int e = 0;
            while (tile >= pfx[e + 1]) e++;
            int m0 = (tile - pfx[e]) * BM;
            int nr = min(BM, c[e] - m0);
            int rel = tile - begin;
            int buf = rel & 1;
            uint32_t par = (uint32_t)((rel >> 1) & 1);

            if (e != cur_e) {
                breg = __ldg(bias + e * CO + sub * 32 + lane);
                cur_e = e;
            }

            // Prefetch this tile's row indices (latency hidden by mbar wait).
            int i0 = __ldg(&g_row_idx[e][m0 + ch * 64 + lane]);
            int i1 = __ldg(&g_row_idx[e][m0 + ch * 64 + 32 + lane]);

            mbar_wait(s_ctrl + 8 + 8u * (uint32_t)buf, par);
            asm volatile("tcgen05.fence::after_thread_sync;" ::: "memory");

            uint32_t d[64];
            uint32_t td = tmem + (uint32_t)buf * 128u + (uint32_t)ch * 64u;
#pragma unroll
            for (int b = 0; b < 2; b++) {
                asm volatile(
                    "tcgen05.ld.sync.aligned.32x32b.x32.b32 "
                    "{%0, %1, %2, %3, %4, %5, %6, %7, "
                    " %8, %9, %10, %11, %12, %13, %14, %15, "
                    " %16, %17, %18, %19, %20, %21, %22, %23, "
                    " %24, %25, %26, %27, %28, %29, %30, %31}, [%32];"
                    : "=r"(d[b*32+0]),  "=r"(d[b*32+1]),  "=r"(d[b*32+2]),  "=r"(d[b*32+3]),
                      "=r"(d[b*32+4]),  "=r"(d[b*32+5]),  "=r"(d[b*32+6]),  "=r"(d[b*32+7]),
                      "=r"(d[b*32+8]),  "=r"(d[b*32+9]),  "=r"(d[b*32+10]), "=r"(d[b*32+11]),
                      "=r"(d[b*32+12]), "=r"(d[b*32+13]), "=r"(d[b*32+14]), "=r"(d[b*32+15]),
                      "=r"(d[b*32+16]), "=r"(d[b*32+17]), "=r"(d[b*32+18]), "=r"(d[b*32+19]),
                      "=r"(d[b*32+20]), "=r"(d[b*32+21]), "=r"(d[b*32+22]), "=r"(d[b*32+23]),
                      "=r"(d[b*32+24]), "=r"(d[b*32+25]), "=r"(d[b*32+26]), "=r"(d[b*32+27]),
                      "=r"(d[b*32+28]), "=r"(d[b*32+29]), "=r"(d[b*32+30]), "=r"(d[b*32+31])
                    : "r"(td + (uint32_t)b * 32u));
            }
            asm volatile("tcgen05.wait::ld.sync.aligned;" ::: "memory");

            // D[buf] fully read -> release to producer (before the stores).
            asm volatile("mbarrier.arrive.shared.b64 _, [%0];"
                         :: "r"(s_ctrl + 24 + 8u * (uint32_t)buf) : "memory");

            // Store: col j = gathered row ch*64+j; 32 lanes = one 128B line.
#pragma unroll
            for (int j = 0; j < 64; j++) {
                int m = ch * 64 + j;
                if (m < nr) {
                    int grow = __shfl_sync(0xffffffffu, (j < 32) ? i0 : i1, j & 31);
                    out[(size_t)grow * CO + sub * 32 + lane] =
                        fmaxf(__uint_as_float(d[j]) + breg, 0.f);
                }
            }
        }
    }

    __syncthreads();
    if (t == 0) {
        asm volatile("mbarrier.inval.shared.b64 [%0];" :: "r"(s_ctrl + 8) : "memory");
        asm volatile("mbarrier.inval.shared.b64 [%0];" :: "r"(s_ctrl + 16) : "memory");
        asm volatile("mbarrier.inval.shared.b64 [%0];" :: "r"(s_ctrl + 24) : "memory");
        asm volatile("mbarrier.inval.shared.b64 [%0];" :: "r"(s_ctrl + 32) : "memory");
    }
    __syncthreads();
    if (wid == 0) {
        asm volatile("tcgen05.dealloc.cta_group::1.sync.aligned.b32 %0, %1;"
                     :: "r"(tmem), "r"(256u));
    }
    if (blockIdx.x == 0 && t < NB) g_count[t] = 0;
#endif
}

// ---------------- launch -----------------------------------------------------
extern "C" void kernel_launch(void* const* d_in, const int* in_sizes, int n_in,
                              void* d_out, int out_size) {
    const float* x = (const float*)d_in[0];
    const int* atom_numbers = (const int*)d_in[1];
    const float* W = (const float*)d_in[2];
    const float* bias = (const float*)d_in[3];
    const int* atom_cases = (const int*)d_in[4];
    float* out = (float*)d_out;

    int nrows = in_sizes[1];  // B * A
    int nscatter = (nrows + 1023) / 1024;

    k_prep<<<nscatter + NE, 1024>>>(atom_numbers, atom_cases, W, out, nrows, nscatter);

    cudaFuncSetAttribute(k_gemm, cudaFuncAttributeMaxDynamicSharedMemorySize, SMEM_BYTES);
    k_gemm<<<NCTA, NT, SMEM_BYTES>>>(x, W, bias, out);
}